// round 3
// baseline (speedup 1.0000x reference)
#include <cuda_runtime.h>
#include <math.h>

#define N_NODES 50000
#define NFEAT   64
#define NHID    64
#define E_REAL  200000
#define E_NHOP  40000
#define E_ALL   240000
#define N_REL   200
#define OUTF    128
#define ALPHA   0.2f

typedef unsigned long long ull;

// ---------------- device scratch ----------------
// P1 layout: [i][dir*256 + role*128 + h*64 + j]
__device__ __align__(16) float g_P1all[(size_t)N_NODES * 512];
// Q1 layout: [e][dir*128 + h*64 + j]
__device__ __align__(16) float g_Q1all[(size_t)E_REAL * 256];
// R1proj: [r][dir*128 + h*64 + j]
__device__ __align__(16) float g_R1proj[N_REL * 256];
__device__ __align__(16) float g_rel2[N_REL * OUTF];
__device__ __align__(16) float g_R2proj[N_REL * OUTF];
__device__ float g_rowsum1[4][N_NODES];                            // [dir*2+h][i]
__device__ __align__(16) float g_hp1[2][(size_t)N_NODES * 128];    // [dir][i*128 + h*64 + j]
__device__ __align__(16) float g_xs[2][(size_t)N_NODES * OUTF];
__device__ __align__(16) float g_P2all[2][(size_t)N_NODES * 256];  // [xs][i][role*128 + j]
__device__ float g_rowsum2[2][N_NODES];
__device__ __align__(16) float g_hp2[2][(size_t)N_NODES * OUTF];
__device__ __align__(16) float g_y[2][(size_t)N_NODES * OUTF];
__device__ float g_wsum[2];
// packed weights (row-major [n][K])
__device__ __align__(16) float g_Wp1[512 * 64];
__device__ __align__(16) float g_WpQ[256 * 64];
__device__ __align__(16) float g_Wp2[256 * 128];

#define RED4(ptr, a, b, c, d) \
    asm volatile("red.global.add.v4.f32 [%0], {%1, %2, %3, %4};" :: "l"(ptr), "f"(a), "f"(b), "f"(c), "f"(d) : "memory")

// ---------------- fused prologue: zero + pack + relation tables ----------------
#define ZB 640
__global__ void prep(const float* __restrict__ a_in, const float* __restrict__ a_out,
                     const float* __restrict__ a_o, const float* __restrict__ rel,
                     const float* __restrict__ W, float* __restrict__ out_tail) {
    int b = blockIdx.x, t = threadIdx.x;
    if (b < ZB) {
        size_t tid = (size_t)b * 256 + t, stride = (size_t)ZB * 256;
        float4 z = make_float4(0.f, 0.f, 0.f, 0.f);
        float4* hp1 = (float4*)&g_hp1[0][0];
        for (size_t i = tid; i < (size_t)2 * N_NODES * 128 / 4; i += stride) hp1[i] = z;
        float4* hp2 = (float4*)&g_hp2[0][0];
        for (size_t i = tid; i < (size_t)2 * N_NODES * 128 / 4; i += stride) hp2[i] = z;
        float4* rs1 = (float4*)&g_rowsum1[0][0];
        for (size_t i = tid; i < (size_t)4 * N_NODES / 4; i += stride) rs1[i] = z;
        float4* rs2 = (float4*)&g_rowsum2[0][0];
        for (size_t i = tid; i < (size_t)2 * N_NODES / 4; i += stride) rs2[i] = z;
        if (tid < 2) g_wsum[tid] = 0.f;
    } else if (b < ZB + 4) {
        // weight packing
        int idx0 = (b - ZB) * 256 + t;
        for (int idx = idx0; idx < 512 * 64; idx += 4 * 256) {
            int n = idx >> 6, k = idx & 63;
            int dir = n >> 8, rem = n & 255, role = rem >> 7, h = (rem >> 6) & 1, j = n & 63;
            const float* A = (dir ? a_out : a_in) + (size_t)h * 64 * 192;
            g_Wp1[idx] = A[j * 192 + role * 64 + k];
        }
        for (int idx = idx0; idx < 256 * 64; idx += 4 * 256) {
            int n = idx >> 6, k = idx & 63;
            int dir = n >> 7, h = (n >> 6) & 1, j = n & 63;
            const float* A = (dir ? a_out : a_in) + (size_t)h * 64 * 192;
            g_WpQ[idx] = A[j * 192 + 128 + k];
        }
        for (int idx = idx0; idx < 256 * 128; idx += 4 * 256) {
            int n = idx >> 7, k = idx & 127;
            int role = n >> 7, j = n & 127;
            g_Wp2[idx] = a_o[j * 384 + role * 128 + k];
        }
    } else if (b < ZB + 12) {
        // rel2 = rel @ W, rows [base, base+25)
        int base = (b - ZB - 4) * 25;
        for (int idx = t; idx < 25 * 128; idx += 256) {
            int r = base + (idx >> 7), j = idx & 127;
            float acc = 0.f;
            #pragma unroll
            for (int k = 0; k < 64; k++) acc += rel[r * 64 + k] * W[k * 128 + j];
            g_rel2[r * 128 + j] = acc;
            out_tail[(size_t)N_NODES * OUTF + r * 128 + j] = acc;
        }
    } else if (b < ZB + 20) {
        // R1proj rows [base, base+25), 256 cols
        int base = (b - ZB - 12) * 25;
        for (int idx = t; idx < 25 * 256; idx += 256) {
            int r = base + (idx >> 8), n = idx & 255;
            int dir = n >> 7, h = (n >> 6) & 1, j = n & 63;
            const float* A = (dir ? a_out : a_in) + (size_t)h * 64 * 192;
            float acc = 0.f;
            #pragma unroll
            for (int k = 0; k < 64; k++) acc += rel[r * 64 + k] * A[j * 192 + 128 + k];
            g_R1proj[r * 256 + n] = acc;
        }
    } else if (b < ZB + 28) {
        // R2proj = rel @ T, T[k][j] = sum_m W[k][m] * a_o[j][256+m]
        __shared__ float T[64 * 128];
        for (int idx = t; idx < 64 * 128; idx += 256) {
            int k = idx >> 7, j = idx & 127;
            float acc = 0.f;
            #pragma unroll 8
            for (int m = 0; m < 128; m++) acc += W[k * 128 + m] * a_o[j * 384 + 256 + m];
            T[idx] = acc;
        }
        __syncthreads();
        int base = (b - ZB - 20) * 25;
        for (int idx = t; idx < 25 * 128; idx += 256) {
            int r = base + (idx >> 7), j = idx & 127;
            float acc = 0.f;
            #pragma unroll
            for (int k = 0; k < 64; k++) acc += rel[r * 64 + k] * T[k * 128 + j];
            g_R2proj[r * 128 + j] = acc;
        }
    }
}

// ---------------- f32x2 packed GEMM ----------------
// C[i][jb+j] = sum_k X[i][k] * Wp[(jb+j)][k]; 128x128 block tile, 256 threads, 8x8/thread
__global__ void gemm_f32x2(const float* __restrict__ X,
                           const float* __restrict__ Wp,
                           float* __restrict__ C,
                           int M, int N, int K) {
    __shared__ float2 Xs2[32][128];  // [kk][i] duplicated {x,x}
    __shared__ float2 As2[32][64];   // [kk][pi]: pair (tx+32q, tx+32q+16)
    int t = threadIdx.x;
    int tx = t & 15, ty = t >> 4;
    int ib = blockIdx.x * 128;
    int jb = blockIdx.y * 128;
    ull acc[8][4];
    #pragma unroll
    for (int ii = 0; ii < 8; ii++)
        #pragma unroll
        for (int q = 0; q < 4; q++) acc[ii][q] = 0ull;

    for (int kc = 0; kc < K; kc += 32) {
        #pragma unroll
        for (int p = t; p < 1024; p += 256) {
            int i = p >> 3, kq = (p & 7) * 4;
            int gi = ib + i;
            float4 v = make_float4(0.f, 0.f, 0.f, 0.f);
            if (gi < M) v = *(const float4*)&X[(size_t)gi * K + kc + kq];
            Xs2[kq + 0][i] = make_float2(v.x, v.x);
            Xs2[kq + 1][i] = make_float2(v.y, v.y);
            Xs2[kq + 2][i] = make_float2(v.z, v.z);
            Xs2[kq + 3][i] = make_float2(v.w, v.w);
        }
        #pragma unroll
        for (int p = t; p < 1024; p += 256) {
            int j = p >> 3, kq = (p & 7) * 4;
            float4 v = *(const float4*)&Wp[(size_t)(jb + j) * K + kc + kq];
            int pi = (j & 15) + 16 * (j >> 5);
            if (j & 16) {
                As2[kq + 0][pi].y = v.x; As2[kq + 1][pi].y = v.y;
                As2[kq + 2][pi].y = v.z; As2[kq + 3][pi].y = v.w;
            } else {
                As2[kq + 0][pi].x = v.x; As2[kq + 1][pi].x = v.y;
                As2[kq + 2][pi].x = v.z; As2[kq + 3][pi].x = v.w;
            }
        }
        __syncthreads();
        #pragma unroll 8
        for (int kk = 0; kk < 32; kk++) {
            ull av[4];
            #pragma unroll
            for (int q = 0; q < 4; q++)
                av[q] = *(const ull*)&As2[kk][tx + 16 * q];
            #pragma unroll
            for (int ii = 0; ii < 8; ii++) {
                ull xx = *(const ull*)&Xs2[kk][ty * 8 + ii];
                #pragma unroll
                for (int q = 0; q < 4; q++)
                    asm("fma.rn.f32x2 %0, %1, %2, %0;"
                        : "+l"(acc[ii][q]) : "l"(xx), "l"(av[q]));
            }
        }
        __syncthreads();
    }
    #pragma unroll
    for (int ii = 0; ii < 8; ii++) {
        int gi = ib + ty * 8 + ii;
        if (gi < M) {
            #pragma unroll
            for (int q = 0; q < 4; q++) {
                float lo, hi;
                asm("mov.b64 {%0, %1}, %2;" : "=f"(lo), "=f"(hi) : "l"(acc[ii][q]));
                C[(size_t)gi * N + jb + tx + 32 * q] = lo;
                C[(size_t)gi * N + jb + tx + 32 * q + 16] = hi;
            }
        }
    }
}

// ---------------- layer-1 edge pass: warp per (dir, edge), both heads ----------------
__global__ void edge_pass1(const int* __restrict__ el, const int* __restrict__ eln,
                           const int* __restrict__ etn,
                           const float* __restrict__ a2_in, const float* __restrict__ a2_out) {
    int dir = blockIdx.y;
    int e = blockIdx.x * 8 + (threadIdx.x >> 5);
    int lane = threadIdx.x & 31;
    int h = lane >> 4;
    int jj = 4 * (lane & 15);
    int i0, i1;
    float4 q;
    if (e < E_REAL) {
        i0 = el[e]; i1 = el[E_REAL + e];
        q = *(const float4*)&g_Q1all[(size_t)e * 256 + dir * 128 + h * 64 + jj];
    } else {
        int en = e - E_REAL;
        i0 = eln[en]; i1 = eln[E_NHOP + en];
        int t0 = etn[2 * en], t1 = etn[2 * en + 1];
        float4 qa = *(const float4*)&g_R1proj[t0 * 256 + dir * 128 + h * 64 + jj];
        float4 qb = *(const float4*)&g_R1proj[t1 * 256 + dir * 128 + h * 64 + jj];
        q.x = qa.x + qb.x; q.y = qa.y + qb.y; q.z = qa.z + qb.z; q.w = qa.w + qb.w;
    }
    int src = dir ? i1 : i0;
    int dst = dir ? i0 : i1;
    float4 p = *(const float4*)&g_P1all[(size_t)src * 512 + dir * 256 + h * 64 + jj];
    float4 d = *(const float4*)&g_P1all[(size_t)dst * 512 + dir * 256 + 128 + h * 64 + jj];
    float m0 = p.x + d.x + q.x;
    float m1 = p.y + d.y + q.y;
    float m2 = p.z + d.z + q.z;
    float m3 = p.w + d.w + q.w;
    const float* a2 = (dir ? a2_out : a2_in) + h * 64 + jj;
    float part = m0 * a2[0] + m1 * a2[1] + m2 * a2[2] + m3 * a2[3];
    #pragma unroll
    for (int o = 8; o; o >>= 1) part += __shfl_xor_sync(0xffffffffu, part, o);
    float lk = part > 0.f ? part : ALPHA * part;
    float ev = expf(-lk);
    float* hp = &g_hp1[dir][(size_t)src * 128 + h * 64 + jj];
    RED4(hp, ev * m0, ev * m1, ev * m2, ev * m3);
    if ((lane & 15) == 0) atomicAdd(&g_rowsum1[dir * 2 + h][src], ev);
}

// ---------------- normalize + elu -> x_s ----------------
__global__ void norm1() {
    int dir = blockIdx.y;
    int idx = blockIdx.x * 256 + threadIdx.x;
    if (idx >= N_NODES * 128) return;
    int i = idx >> 7, kk = idx & 127;
    int h = kk >> 6;
    float rs = g_rowsum1[dir * 2 + h][i];
    float v = g_hp1[dir][idx];
    v = (rs > 0.f) ? v / rs : 0.f;
    v = (v > 0.f) ? v : expm1f(v);
    g_xs[dir][idx] = v;
}

// ---------------- layer-2 edge pass ----------------
__global__ void edge_pass2(const int* __restrict__ el, const int* __restrict__ eln,
                           const int* __restrict__ et, const int* __restrict__ etn,
                           const float* __restrict__ a2_o) {
    int dir = blockIdx.y;
    int e = blockIdx.x * 8 + (threadIdx.x >> 5);
    int lane = threadIdx.x & 31;
    int i0, i1;
    float q0, q1, q2, q3;
    if (e < E_REAL) {
        i0 = el[e]; i1 = el[E_REAL + e];
        int ty = et[e];
        float4 qv = *(const float4*)&g_R2proj[ty * 128 + 4 * lane];
        q0 = qv.x; q1 = qv.y; q2 = qv.z; q3 = qv.w;
    } else {
        int en = e - E_REAL;
        i0 = eln[en]; i1 = eln[E_NHOP + en];
        int t0 = etn[2 * en], t1 = etn[2 * en + 1];
        float4 qa = *(const float4*)&g_R2proj[t0 * 128 + 4 * lane];
        float4 qb = *(const float4*)&g_R2proj[t1 * 128 + 4 * lane];
        q0 = qa.x + qb.x; q1 = qa.y + qb.y; q2 = qa.z + qb.z; q3 = qa.w + qb.w;
    }
    int seg = dir ? i1 : i0;
    int nbr = dir ? i0 : i1;
    float4 pv = *(const float4*)&g_P2all[dir][(size_t)seg * 256 + 4 * lane];
    float4 dv = *(const float4*)&g_P2all[dir][(size_t)nbr * 256 + 128 + 4 * lane];
    float m0 = pv.x + dv.x + q0;
    float m1 = pv.y + dv.y + q1;
    float m2 = pv.z + dv.z + q2;
    float m3 = pv.w + dv.w + q3;
    float4 av = *(const float4*)&a2_o[4 * lane];
    float part = m0 * av.x + m1 * av.y + m2 * av.z + m3 * av.w;
    #pragma unroll
    for (int o = 16; o; o >>= 1) part += __shfl_xor_sync(0xffffffffu, part, o);
    float lk = part > 0.f ? part : ALPHA * part;
    float ev = expf(-lk);
    float* hp = &g_hp2[dir][(size_t)seg * 128 + 4 * lane];
    RED4(hp, ev * m0, ev * m1, ev * m2, ev * m3);
    if (lane == 0) atomicAdd(&g_rowsum2[dir][seg], ev);
}

// ---------------- layer-2 normalize + elu + attention scores ----------------
__global__ void node_final1(const float* __restrict__ We, const float* __restrict__ be,
                            const float* __restrict__ qe) {
    int xs = blockIdx.y;
    int w = threadIdx.x >> 5;
    int lane = threadIdx.x & 31;
    int node = blockIdx.x * 8 + w;
    if (node >= N_NODES) return;
    __shared__ float ysm[8][128];
    float rs = g_rowsum2[xs][node];
    float inv = (rs > 0.f) ? 1.f / rs : 0.f;
    #pragma unroll
    for (int u = 0; u < 4; u++) {
        int k = 4 * lane + u;
        float v = g_hp2[xs][(size_t)node * 128 + k] * inv;
        v = (v > 0.f) ? v : expm1f(v);
        ysm[w][k] = v;
        g_y[xs][(size_t)node * 128 + k] = v;
    }
    __syncwarp();
    float wp = 0.f;
    #pragma unroll
    for (int half = 0; half < 2; half++) {
        int j = lane + 32 * half;
        float acc = be[j];
        #pragma unroll 8
        for (int k = 0; k < 128; k++) acc += ysm[w][k] * We[k * 64 + j];
        wp += tanhf(acc) * qe[j];
    }
    #pragma unroll
    for (int o = 16; o; o >>= 1) wp += __shfl_xor_sync(0xffffffffu, wp, o);
    if (lane == 0) atomicAdd(&g_wsum[xs], wp);
}

// ---------------- beta + combine (fused) ----------------
__global__ void combine(float* __restrict__ out) {
    float m0 = g_wsum[0] / (float)N_NODES;
    float m1 = g_wsum[1] / (float)N_NODES;
    float mx = fmaxf(m0, m1);
    float e0 = expf(m0 - mx), e1 = expf(m1 - mx);
    float b0 = e0 / (e0 + e1), b1 = e1 / (e0 + e1);
    size_t i = (size_t)blockIdx.x * 256 + threadIdx.x;
    if (i >= (size_t)N_NODES * OUTF) return;
    out[i] = b0 * g_y[0][i] + b1 * g_y[1][i];
}

// ---------------- launch ----------------
extern "C" void kernel_launch(void* const* d_in, const int* in_sizes, int n_in,
                              void* d_out, int out_size) {
    const float* ent   = (const float*)d_in[0];
    const float* rel   = (const float*)d_in[1];
    const int*   el    = (const int*)d_in[2];
    const int*   et    = (const int*)d_in[3];
    const float* eemb  = (const float*)d_in[4];
    const int*   eln   = (const int*)d_in[5];
    const int*   etn   = (const int*)d_in[6];
    const float* a_in  = (const float*)d_in[7];
    const float* a2_in = (const float*)d_in[8];
    const float* a_out = (const float*)d_in[9];
    const float* a2_out= (const float*)d_in[10];
    const float* a_o   = (const float*)d_in[11];
    const float* a2_o  = (const float*)d_in[12];
    const float* W     = (const float*)d_in[13];
    const float* We    = (const float*)d_in[14];
    const float* be    = (const float*)d_in[15];
    const float* qe    = (const float*)d_in[16];
    float* out = (float*)d_out;

    float *p1 = 0, *q1 = 0, *xsb = 0, *p2 = 0, *wp1 = 0, *wpq = 0, *wp2 = 0;
    cudaGetSymbolAddress((void**)&p1, g_P1all);
    cudaGetSymbolAddress((void**)&q1, g_Q1all);
    cudaGetSymbolAddress((void**)&xsb, g_xs);
    cudaGetSymbolAddress((void**)&p2, g_P2all);
    cudaGetSymbolAddress((void**)&wp1, g_Wp1);
    cudaGetSymbolAddress((void**)&wpq, g_WpQ);
    cudaGetSymbolAddress((void**)&wp2, g_Wp2);

    prep<<<ZB + 28, 256>>>(a_in, a_out, a_o, rel, W, out);

    gemm_f32x2<<<dim3((N_NODES + 127) / 128, 4), 256>>>(ent, wp1, p1, N_NODES, 512, 64);
    gemm_f32x2<<<dim3((E_REAL + 127) / 128, 2), 256>>>(eemb, wpq, q1, E_REAL, 256, 64);

    edge_pass1<<<dim3(E_ALL / 8, 2), 256>>>(el, eln, etn, a2_in, a2_out);
    norm1<<<dim3((N_NODES * 128 + 255) / 256, 2), 256>>>();

    for (int xs = 0; xs < 2; xs++)
        gemm_f32x2<<<dim3((N_NODES + 127) / 128, 2), 256>>>(
            xsb + (size_t)xs * N_NODES * 128, wp2,
            p2 + (size_t)xs * N_NODES * 256, N_NODES, 256, 128);

    edge_pass2<<<dim3(E_ALL / 8, 2), 256>>>(el, eln, et, etn, a2_o);
    node_final1<<<dim3((N_NODES + 7) / 8, 2), 256>>>(We, be, qe);
    combine<<<(N_NODES * OUTF + 255) / 256, 256>>>(out);
}

// round 4
// speedup vs baseline: 1.0026x; 1.0026x over previous
#include <cuda_runtime.h>
#include <math.h>

#define N_NODES 50000
#define NFEAT   64
#define NHID    64
#define E_REAL  200000
#define E_NHOP  40000
#define E_ALL   240000
#define N_REL   200
#define OUTF    128
#define ALPHA   0.2f

typedef unsigned long long ull;

// ---------------- device scratch ----------------
// P1 layout: [i][dir*256 + role*128 + h*64 + j]
__device__ __align__(16) float g_P1all[(size_t)N_NODES * 512];
// Q1 layout: [e][dir*128 + h*64 + j]
__device__ __align__(16) float g_Q1all[(size_t)E_REAL * 256];
// R1proj: [r][dir*128 + h*64 + j]
__device__ __align__(16) float g_R1proj[N_REL * 256];
__device__ __align__(16) float g_rel2[N_REL * OUTF];
__device__ __align__(16) float g_R2proj[N_REL * OUTF];
__device__ float g_rowsum1[4][N_NODES];                            // [dir*2+h][i]
__device__ __align__(16) float g_hp1[2][(size_t)N_NODES * 128];    // [dir][i*128 + h*64 + j]
__device__ __align__(16) float g_xs[2][(size_t)N_NODES * OUTF];
__device__ __align__(16) float g_P2all[2][(size_t)N_NODES * 256];  // [xs][i][role*128 + j]
__device__ float g_rowsum2[2][N_NODES];
__device__ __align__(16) float g_hp2[2][(size_t)N_NODES * OUTF];
__device__ __align__(16) float g_y[2][(size_t)N_NODES * OUTF];
__device__ float g_wsum[2];
// packed weights (row-major [n][K])
__device__ __align__(16) float g_Wp1[512 * 64];
__device__ __align__(16) float g_WpQ[256 * 64];
__device__ __align__(16) float g_Wp2[256 * 128];

#define RED4(ptr, a, b, c, d) \
    asm volatile("red.global.add.v4.f32 [%0], {%1, %2, %3, %4};" :: "l"(ptr), "f"(a), "f"(b), "f"(c), "f"(d) : "memory")

// ---------------- fused prologue: zero + pack + relation tables ----------------
#define ZB 640
__global__ void prep(const float* __restrict__ a_in, const float* __restrict__ a_out,
                     const float* __restrict__ a_o, const float* __restrict__ rel,
                     const float* __restrict__ W, float* __restrict__ out_tail) {
    int b = blockIdx.x, t = threadIdx.x;
    if (b < ZB) {
        size_t tid = (size_t)b * 256 + t, stride = (size_t)ZB * 256;
        float4 z = make_float4(0.f, 0.f, 0.f, 0.f);
        float4* hp1 = (float4*)&g_hp1[0][0];
        for (size_t i = tid; i < (size_t)2 * N_NODES * 128 / 4; i += stride) hp1[i] = z;
        float4* hp2 = (float4*)&g_hp2[0][0];
        for (size_t i = tid; i < (size_t)2 * N_NODES * 128 / 4; i += stride) hp2[i] = z;
        float4* rs1 = (float4*)&g_rowsum1[0][0];
        for (size_t i = tid; i < (size_t)4 * N_NODES / 4; i += stride) rs1[i] = z;
        float4* rs2 = (float4*)&g_rowsum2[0][0];
        for (size_t i = tid; i < (size_t)2 * N_NODES / 4; i += stride) rs2[i] = z;
        if (tid < 2) g_wsum[tid] = 0.f;
    } else if (b < ZB + 4) {
        int idx0 = (b - ZB) * 256 + t;
        for (int idx = idx0; idx < 512 * 64; idx += 4 * 256) {
            int n = idx >> 6, k = idx & 63;
            int dir = n >> 8, rem = n & 255, role = rem >> 7, h = (rem >> 6) & 1, j = n & 63;
            const float* A = (dir ? a_out : a_in) + (size_t)h * 64 * 192;
            g_Wp1[idx] = A[j * 192 + role * 64 + k];
        }
        for (int idx = idx0; idx < 256 * 64; idx += 4 * 256) {
            int n = idx >> 6, k = idx & 63;
            int dir = n >> 7, h = (n >> 6) & 1, j = n & 63;
            const float* A = (dir ? a_out : a_in) + (size_t)h * 64 * 192;
            g_WpQ[idx] = A[j * 192 + 128 + k];
        }
        for (int idx = idx0; idx < 256 * 128; idx += 4 * 256) {
            int n = idx >> 7, k = idx & 127;
            int role = n >> 7, j = n & 127;
            g_Wp2[idx] = a_o[j * 384 + role * 128 + k];
        }
    } else if (b < ZB + 12) {
        int base = (b - ZB - 4) * 25;
        for (int idx = t; idx < 25 * 128; idx += 256) {
            int r = base + (idx >> 7), j = idx & 127;
            float acc = 0.f;
            #pragma unroll
            for (int k = 0; k < 64; k++) acc += rel[r * 64 + k] * W[k * 128 + j];
            g_rel2[r * 128 + j] = acc;
            out_tail[(size_t)N_NODES * OUTF + r * 128 + j] = acc;
        }
    } else if (b < ZB + 20) {
        int base = (b - ZB - 12) * 25;
        for (int idx = t; idx < 25 * 256; idx += 256) {
            int r = base + (idx >> 8), n = idx & 255;
            int dir = n >> 7, h = (n >> 6) & 1, j = n & 63;
            const float* A = (dir ? a_out : a_in) + (size_t)h * 64 * 192;
            float acc = 0.f;
            #pragma unroll
            for (int k = 0; k < 64; k++) acc += rel[r * 64 + k] * A[j * 192 + 128 + k];
            g_R1proj[r * 256 + n] = acc;
        }
    } else if (b < ZB + 28) {
        __shared__ float T[64 * 128];
        for (int idx = t; idx < 64 * 128; idx += 256) {
            int k = idx >> 7, j = idx & 127;
            float acc = 0.f;
            #pragma unroll 8
            for (int m = 0; m < 128; m++) acc += W[k * 128 + m] * a_o[j * 384 + 256 + m];
            T[idx] = acc;
        }
        __syncthreads();
        int base = (b - ZB - 20) * 25;
        for (int idx = t; idx < 25 * 128; idx += 256) {
            int r = base + (idx >> 7), j = idx & 127;
            float acc = 0.f;
            #pragma unroll
            for (int k = 0; k < 64; k++) acc += rel[r * 64 + k] * T[k * 128 + j];
            g_R2proj[r * 128 + j] = acc;
        }
    }
}

// ---------------- f32x2 packed GEMM (conflict-free SMEM, KC=16) ----------------
// C[i][jb+j] = sum_k X[i][k] * Wp[(jb+j)][k]; 128x128 block tile, 256 threads, 8x8/thread
#define KC 16
__global__ void gemm_f32x2(const float* __restrict__ X,
                           const float* __restrict__ Wp,
                           float* __restrict__ C,
                           int M, int N, int K) {
    __shared__ float2 Xs2[KC][129];  // [kk][i] duplicated {x,x}, padded row
    __shared__ float2 As2[KC][65];   // [kk][pi]: pair (tx+32q, tx+32q+16), pi = tx+16q
    int t = threadIdx.x;
    int tx = t & 15, ty = t >> 4;
    int ib = blockIdx.x * 128;
    int jb = blockIdx.y * 128;
    ull acc[8][4];
    #pragma unroll
    for (int ii = 0; ii < 8; ii++)
        #pragma unroll
        for (int q = 0; q < 4; q++) acc[ii][q] = 0ull;

    for (int kc = 0; kc < K; kc += KC) {
        // X tile: 128 i x 16 k. p: i = p&127 (consec lanes -> consec i, conflict-free)
        #pragma unroll
        for (int p = t; p < 512; p += 256) {
            int i = p & 127, kq = (p >> 7) * 4;
            int gi = ib + i;
            float4 v = make_float4(0.f, 0.f, 0.f, 0.f);
            if (gi < M) v = *(const float4*)&X[(size_t)gi * K + kc + kq];
            Xs2[kq + 0][i] = make_float2(v.x, v.x);
            Xs2[kq + 1][i] = make_float2(v.y, v.y);
            Xs2[kq + 2][i] = make_float2(v.z, v.z);
            Xs2[kq + 3][i] = make_float2(v.w, v.w);
        }
        // A tile: 128 j x 16 k. j = p&127: lanes 0-15 .x (even banks), 16-31 .y (odd) -> conflict-free
        #pragma unroll
        for (int p = t; p < 512; p += 256) {
            int j = p & 127, kq = (p >> 7) * 4;
            float4 v = *(const float4*)&Wp[(size_t)(jb + j) * K + kc + kq];
            int pi = (j & 15) + 16 * (j >> 5);
            if (j & 16) {
                As2[kq + 0][pi].y = v.x; As2[kq + 1][pi].y = v.y;
                As2[kq + 2][pi].y = v.z; As2[kq + 3][pi].y = v.w;
            } else {
                As2[kq + 0][pi].x = v.x; As2[kq + 1][pi].x = v.y;
                As2[kq + 2][pi].x = v.z; As2[kq + 3][pi].x = v.w;
            }
        }
        __syncthreads();
        #pragma unroll 8
        for (int kk = 0; kk < KC; kk++) {
            ull av[4];
            #pragma unroll
            for (int q = 0; q < 4; q++)
                av[q] = *(const ull*)&As2[kk][tx + 16 * q];
            #pragma unroll
            for (int ii = 0; ii < 8; ii++) {
                ull xx = *(const ull*)&Xs2[kk][ty * 8 + ii];
                #pragma unroll
                for (int q = 0; q < 4; q++)
                    asm("fma.rn.f32x2 %0, %1, %2, %0;"
                        : "+l"(acc[ii][q]) : "l"(xx), "l"(av[q]));
            }
        }
        __syncthreads();
    }
    #pragma unroll
    for (int ii = 0; ii < 8; ii++) {
        int gi = ib + ty * 8 + ii;
        if (gi < M) {
            #pragma unroll
            for (int q = 0; q < 4; q++) {
                float lo, hi;
                asm("mov.b64 {%0, %1}, %2;" : "=f"(lo), "=f"(hi) : "l"(acc[ii][q]));
                C[(size_t)gi * N + jb + tx + 32 * q] = lo;
                C[(size_t)gi * N + jb + tx + 32 * q + 16] = hi;
            }
        }
    }
}

// ---------------- layer-1 edge pass: warp per (dir, edge), both heads ----------------
__global__ void edge_pass1(const int* __restrict__ el, const int* __restrict__ eln,
                           const int* __restrict__ etn,
                           const float* __restrict__ a2_in, const float* __restrict__ a2_out) {
    int dir = blockIdx.y;
    int e = blockIdx.x * 8 + (threadIdx.x >> 5);
    int lane = threadIdx.x & 31;
    int h = lane >> 4;
    int jj = 4 * (lane & 15);
    int i0, i1;
    float4 q;
    if (e < E_REAL) {
        i0 = el[e]; i1 = el[E_REAL + e];
        q = *(const float4*)&g_Q1all[(size_t)e * 256 + dir * 128 + h * 64 + jj];
    } else {
        int en = e - E_REAL;
        i0 = eln[en]; i1 = eln[E_NHOP + en];
        int t0 = etn[2 * en], t1 = etn[2 * en + 1];
        float4 qa = *(const float4*)&g_R1proj[t0 * 256 + dir * 128 + h * 64 + jj];
        float4 qb = *(const float4*)&g_R1proj[t1 * 256 + dir * 128 + h * 64 + jj];
        q.x = qa.x + qb.x; q.y = qa.y + qb.y; q.z = qa.z + qb.z; q.w = qa.w + qb.w;
    }
    int src = dir ? i1 : i0;
    int dst = dir ? i0 : i1;
    float4 p = *(const float4*)&g_P1all[(size_t)src * 512 + dir * 256 + h * 64 + jj];
    float4 d = *(const float4*)&g_P1all[(size_t)dst * 512 + dir * 256 + 128 + h * 64 + jj];
    float m0 = p.x + d.x + q.x;
    float m1 = p.y + d.y + q.y;
    float m2 = p.z + d.z + q.z;
    float m3 = p.w + d.w + q.w;
    const float* a2 = (dir ? a2_out : a2_in) + h * 64 + jj;
    float part = m0 * a2[0] + m1 * a2[1] + m2 * a2[2] + m3 * a2[3];
    #pragma unroll
    for (int o = 8; o; o >>= 1) part += __shfl_xor_sync(0xffffffffu, part, o);
    float lk = part > 0.f ? part : ALPHA * part;
    float ev = expf(-lk);
    float* hp = &g_hp1[dir][(size_t)src * 128 + h * 64 + jj];
    RED4(hp, ev * m0, ev * m1, ev * m2, ev * m3);
    if ((lane & 15) == 0) atomicAdd(&g_rowsum1[dir * 2 + h][src], ev);
}

// ---------------- normalize + elu -> x_s ----------------
__global__ void norm1() {
    int dir = blockIdx.y;
    int idx = blockIdx.x * 256 + threadIdx.x;
    if (idx >= N_NODES * 128) return;
    int i = idx >> 7, kk = idx & 127;
    int h = kk >> 6;
    float rs = g_rowsum1[dir * 2 + h][i];
    float v = g_hp1[dir][idx];
    v = (rs > 0.f) ? v / rs : 0.f;
    v = (v > 0.f) ? v : expm1f(v);
    g_xs[dir][idx] = v;
}

// ---------------- layer-2 edge pass ----------------
__global__ void edge_pass2(const int* __restrict__ el, const int* __restrict__ eln,
                           const int* __restrict__ et, const int* __restrict__ etn,
                           const float* __restrict__ a2_o) {
    int dir = blockIdx.y;
    int e = blockIdx.x * 8 + (threadIdx.x >> 5);
    int lane = threadIdx.x & 31;
    int i0, i1;
    float q0, q1, q2, q3;
    if (e < E_REAL) {
        i0 = el[e]; i1 = el[E_REAL + e];
        int ty = et[e];
        float4 qv = *(const float4*)&g_R2proj[ty * 128 + 4 * lane];
        q0 = qv.x; q1 = qv.y; q2 = qv.z; q3 = qv.w;
    } else {
        int en = e - E_REAL;
        i0 = eln[en]; i1 = eln[E_NHOP + en];
        int t0 = etn[2 * en], t1 = etn[2 * en + 1];
        float4 qa = *(const float4*)&g_R2proj[t0 * 128 + 4 * lane];
        float4 qb = *(const float4*)&g_R2proj[t1 * 128 + 4 * lane];
        q0 = qa.x + qb.x; q1 = qa.y + qb.y; q2 = qa.z + qb.z; q3 = qa.w + qb.w;
    }
    int seg = dir ? i1 : i0;
    int nbr = dir ? i0 : i1;
    float4 pv = *(const float4*)&g_P2all[dir][(size_t)seg * 256 + 4 * lane];
    float4 dv = *(const float4*)&g_P2all[dir][(size_t)nbr * 256 + 128 + 4 * lane];
    float m0 = pv.x + dv.x + q0;
    float m1 = pv.y + dv.y + q1;
    float m2 = pv.z + dv.z + q2;
    float m3 = pv.w + dv.w + q3;
    float4 av = *(const float4*)&a2_o[4 * lane];
    float part = m0 * av.x + m1 * av.y + m2 * av.z + m3 * av.w;
    #pragma unroll
    for (int o = 16; o; o >>= 1) part += __shfl_xor_sync(0xffffffffu, part, o);
    float lk = part > 0.f ? part : ALPHA * part;
    float ev = expf(-lk);
    float* hp = &g_hp2[dir][(size_t)seg * 128 + 4 * lane];
    RED4(hp, ev * m0, ev * m1, ev * m2, ev * m3);
    if (lane == 0) atomicAdd(&g_rowsum2[dir][seg], ev);
}

// ---------------- layer-2 normalize + elu + attention scores ----------------
__global__ void node_final1(const float* __restrict__ We, const float* __restrict__ be,
                            const float* __restrict__ qe) {
    int xs = blockIdx.y;
    int w = threadIdx.x >> 5;
    int lane = threadIdx.x & 31;
    int node = blockIdx.x * 8 + w;
    if (node >= N_NODES) return;
    __shared__ float ysm[8][128];
    float rs = g_rowsum2[xs][node];
    float inv = (rs > 0.f) ? 1.f / rs : 0.f;
    #pragma unroll
    for (int u = 0; u < 4; u++) {
        int k = 4 * lane + u;
        float v = g_hp2[xs][(size_t)node * 128 + k] * inv;
        v = (v > 0.f) ? v : expm1f(v);
        ysm[w][k] = v;
        g_y[xs][(size_t)node * 128 + k] = v;
    }
    __syncwarp();
    float wp = 0.f;
    #pragma unroll
    for (int half = 0; half < 2; half++) {
        int j = lane + 32 * half;
        float acc = be[j];
        #pragma unroll 8
        for (int k = 0; k < 128; k++) acc += ysm[w][k] * We[k * 64 + j];
        wp += tanhf(acc) * qe[j];
    }
    #pragma unroll
    for (int o = 16; o; o >>= 1) wp += __shfl_xor_sync(0xffffffffu, wp, o);
    if (lane == 0) atomicAdd(&g_wsum[xs], wp);
}

// ---------------- beta + combine (fused) ----------------
__global__ void combine(float* __restrict__ out) {
    float m0 = g_wsum[0] / (float)N_NODES;
    float m1 = g_wsum[1] / (float)N_NODES;
    float mx = fmaxf(m0, m1);
    float e0 = expf(m0 - mx), e1 = expf(m1 - mx);
    float b0 = e0 / (e0 + e1), b1 = e1 / (e0 + e1);
    size_t i = (size_t)blockIdx.x * 256 + threadIdx.x;
    if (i >= (size_t)N_NODES * OUTF) return;
    out[i] = b0 * g_y[0][i] + b1 * g_y[1][i];
}

// ---------------- launch ----------------
extern "C" void kernel_launch(void* const* d_in, const int* in_sizes, int n_in,
                              void* d_out, int out_size) {
    const float* ent   = (const float*)d_in[0];
    const float* rel   = (const float*)d_in[1];
    const int*   el    = (const int*)d_in[2];
    const int*   et    = (const int*)d_in[3];
    const float* eemb  = (const float*)d_in[4];
    const int*   eln   = (const int*)d_in[5];
    const int*   etn   = (const int*)d_in[6];
    const float* a_in  = (const float*)d_in[7];
    const float* a2_in = (const float*)d_in[8];
    const float* a_out = (const float*)d_in[9];
    const float* a2_out= (const float*)d_in[10];
    const float* a_o   = (const float*)d_in[11];
    const float* a2_o  = (const float*)d_in[12];
    const float* W     = (const float*)d_in[13];
    const float* We    = (const float*)d_in[14];
    const float* be    = (const float*)d_in[15];
    const float* qe    = (const float*)d_in[16];
    float* out = (float*)d_out;

    float *p1 = 0, *q1 = 0, *xsb = 0, *p2 = 0, *wp1 = 0, *wpq = 0, *wp2 = 0;
    cudaGetSymbolAddress((void**)&p1, g_P1all);
    cudaGetSymbolAddress((void**)&q1, g_Q1all);
    cudaGetSymbolAddress((void**)&xsb, g_xs);
    cudaGetSymbolAddress((void**)&p2, g_P2all);
    cudaGetSymbolAddress((void**)&wp1, g_Wp1);
    cudaGetSymbolAddress((void**)&wpq, g_WpQ);
    cudaGetSymbolAddress((void**)&wp2, g_Wp2);

    prep<<<ZB + 28, 256>>>(a_in, a_out, a_o, rel, W, out);

    gemm_f32x2<<<dim3((N_NODES + 127) / 128, 4), 256>>>(ent, wp1, p1, N_NODES, 512, 64);
    gemm_f32x2<<<dim3((E_REAL + 127) / 128, 2), 256>>>(eemb, wpq, q1, E_REAL, 256, 64);

    edge_pass1<<<dim3(E_ALL / 8, 2), 256>>>(el, eln, etn, a2_in, a2_out);
    norm1<<<dim3((N_NODES * 128 + 255) / 256, 2), 256>>>();

    for (int xs = 0; xs < 2; xs++)
        gemm_f32x2<<<dim3((N_NODES + 127) / 128, 2), 256>>>(
            xsb + (size_t)xs * N_NODES * 128, wp2,
            p2 + (size_t)xs * N_NODES * 256, N_NODES, 256, 128);

    edge_pass2<<<dim3(E_ALL / 8, 2), 256>>>(el, eln, et, etn, a2_o);
    node_final1<<<dim3((N_NODES + 7) / 8, 2), 256>>>(We, be, qe);
    combine<<<(N_NODES * OUTF + 255) / 256, 256>>>(out);
}

// round 5
// speedup vs baseline: 1.0444x; 1.0416x over previous
#include <cuda_runtime.h>
#include <math.h>

#define N_NODES 50000
#define NFEAT   64
#define NHID    64
#define E_REAL  200000
#define E_NHOP  40000
#define E_ALL   240000
#define N_REL   200
#define OUTF    128
#define ALPHA   0.2f

typedef unsigned long long ull;

// ---------------- device scratch ----------------
// P1 layout: [i][dir*256 + role*128 + h*64 + j]
__device__ __align__(16) float g_P1all[(size_t)N_NODES * 512];
// Q1 layout: [e][dir*128 + h*64 + j]
__device__ __align__(16) float g_Q1all[(size_t)E_REAL * 256];
// R1proj: [r][dir*128 + h*64 + j]
__device__ __align__(16) float g_R1proj[N_REL * 256];
__device__ __align__(16) float g_rel2[N_REL * OUTF];
__device__ __align__(16) float g_R2proj[N_REL * OUTF];
__device__ float g_rowsum1[4][N_NODES];                            // [dir*2+h][i]
__device__ __align__(16) float g_hp1[2][(size_t)N_NODES * 128];    // [dir][i*128 + h*64 + j]
__device__ __align__(16) float g_xs[2][(size_t)N_NODES * OUTF];
__device__ __align__(16) float g_P2all[2][(size_t)N_NODES * 256];  // [xs][i][role*128 + j]
__device__ float g_rowsum2[2][N_NODES];
__device__ __align__(16) float g_hp2[2][(size_t)N_NODES * OUTF];
__device__ __align__(16) float g_y[2][(size_t)N_NODES * OUTF];
__device__ float g_wsum[2];
// packed weights (row-major [n][K])
__device__ __align__(16) float g_Wp1[512 * 64];
__device__ __align__(16) float g_WpQ[256 * 64];
__device__ __align__(16) float g_Wp2[256 * 128];

#define RED4(ptr, a, b, c, d) \
    asm volatile("red.global.add.v4.f32 [%0], {%1, %2, %3, %4};" :: "l"(ptr), "f"(a), "f"(b), "f"(c), "f"(d) : "memory")

// ---------------- fused prologue: zero + pack + relation tables ----------------
#define ZB 640
__global__ void prep(const float* __restrict__ a_in, const float* __restrict__ a_out,
                     const float* __restrict__ a_o, const float* __restrict__ rel,
                     const float* __restrict__ W, float* __restrict__ out_tail) {
    int b = blockIdx.x, t = threadIdx.x;
    if (b < ZB) {
        size_t tid = (size_t)b * 256 + t, stride = (size_t)ZB * 256;
        float4 z = make_float4(0.f, 0.f, 0.f, 0.f);
        float4* hp1 = (float4*)&g_hp1[0][0];
        for (size_t i = tid; i < (size_t)2 * N_NODES * 128 / 4; i += stride) hp1[i] = z;
        float4* hp2 = (float4*)&g_hp2[0][0];
        for (size_t i = tid; i < (size_t)2 * N_NODES * 128 / 4; i += stride) hp2[i] = z;
        float4* rs1 = (float4*)&g_rowsum1[0][0];
        for (size_t i = tid; i < (size_t)4 * N_NODES / 4; i += stride) rs1[i] = z;
        float4* rs2 = (float4*)&g_rowsum2[0][0];
        for (size_t i = tid; i < (size_t)2 * N_NODES / 4; i += stride) rs2[i] = z;
        if (tid < 2) g_wsum[tid] = 0.f;
    } else if (b < ZB + 4) {
        int idx0 = (b - ZB) * 256 + t;
        for (int idx = idx0; idx < 512 * 64; idx += 4 * 256) {
            int n = idx >> 6, k = idx & 63;
            int dir = n >> 8, rem = n & 255, role = rem >> 7, h = (rem >> 6) & 1, j = n & 63;
            const float* A = (dir ? a_out : a_in) + (size_t)h * 64 * 192;
            g_Wp1[idx] = A[j * 192 + role * 64 + k];
        }
        for (int idx = idx0; idx < 256 * 64; idx += 4 * 256) {
            int n = idx >> 6, k = idx & 63;
            int dir = n >> 7, h = (n >> 6) & 1, j = n & 63;
            const float* A = (dir ? a_out : a_in) + (size_t)h * 64 * 192;
            g_WpQ[idx] = A[j * 192 + 128 + k];
        }
        for (int idx = idx0; idx < 256 * 128; idx += 4 * 256) {
            int n = idx >> 7, k = idx & 127;
            int role = n >> 7, j = n & 127;
            g_Wp2[idx] = a_o[j * 384 + role * 128 + k];
        }
    } else if (b < ZB + 12) {
        int base = (b - ZB - 4) * 25;
        for (int idx = t; idx < 25 * 128; idx += 256) {
            int r = base + (idx >> 7), j = idx & 127;
            float acc = 0.f;
            #pragma unroll
            for (int k = 0; k < 64; k++) acc += rel[r * 64 + k] * W[k * 128 + j];
            g_rel2[r * 128 + j] = acc;
            out_tail[(size_t)N_NODES * OUTF + r * 128 + j] = acc;
        }
    } else if (b < ZB + 20) {
        int base = (b - ZB - 12) * 25;
        for (int idx = t; idx < 25 * 256; idx += 256) {
            int r = base + (idx >> 8), n = idx & 255;
            int dir = n >> 7, h = (n >> 6) & 1, j = n & 63;
            const float* A = (dir ? a_out : a_in) + (size_t)h * 64 * 192;
            float acc = 0.f;
            #pragma unroll
            for (int k = 0; k < 64; k++) acc += rel[r * 64 + k] * A[j * 192 + 128 + k];
            g_R1proj[r * 256 + n] = acc;
        }
    } else if (b < ZB + 28) {
        __shared__ float T[64 * 128];
        for (int idx = t; idx < 64 * 128; idx += 256) {
            int k = idx >> 7, j = idx & 127;
            float acc = 0.f;
            #pragma unroll 8
            for (int m = 0; m < 128; m++) acc += W[k * 128 + m] * a_o[j * 384 + 256 + m];
            T[idx] = acc;
        }
        __syncthreads();
        int base = (b - ZB - 20) * 25;
        for (int idx = t; idx < 25 * 128; idx += 256) {
            int r = base + (idx >> 7), j = idx & 127;
            float acc = 0.f;
            #pragma unroll
            for (int k = 0; k < 64; k++) acc += rel[r * 64 + k] * T[k * 128 + j];
            g_R2proj[r * 128 + j] = acc;
        }
    }
}

// ---------------- f32x2 packed GEMM (exact R2 version — empirically fastest) ----------------
// C[i][jb+j] = sum_k X[i][k] * Wp[(jb+j)][k]; 128x128 block tile, K chunked by 32;
// 256 threads, 8x8 per-thread tile. Pair pi = tx + 16*q holds columns (tx+32q, tx+32q+16).
__global__ void gemm_f32x2(const float* __restrict__ X,
                           const float* __restrict__ Wp,
                           float* __restrict__ C,
                           int M, int N, int K) {
    __shared__ float Xs[128][33];
    __shared__ float2 As2[32][65];
    int t = threadIdx.x;
    int tx = t & 15, ty = t >> 4;
    int ib = blockIdx.x * 128;
    int jb = blockIdx.y * 128;
    ull acc[8][4];
    #pragma unroll
    for (int ii = 0; ii < 8; ii++)
        #pragma unroll
        for (int q = 0; q < 4; q++) acc[ii][q] = 0ull;

    for (int kc = 0; kc < K; kc += 32) {
        // X tile: 128 rows x 32 cols, float4 loads
        #pragma unroll
        for (int p = t; p < 1024; p += 256) {
            int i = p >> 3, kq = (p & 7) * 4;
            int gi = ib + i;
            float4 v = make_float4(0.f, 0.f, 0.f, 0.f);
            if (gi < M) v = *(const float4*)&X[(size_t)gi * K + kc + kq];
            Xs[i][kq + 0] = v.x; Xs[i][kq + 1] = v.y;
            Xs[i][kq + 2] = v.z; Xs[i][kq + 3] = v.w;
        }
        // A tile: 128 rows (j) x 32 cols (k), transposed + paired into As2
        #pragma unroll
        for (int p = t; p < 1024; p += 256) {
            int j = p >> 3, kq = (p & 7) * 4;
            float4 v = *(const float4*)&Wp[(size_t)(jb + j) * K + kc + kq];
            int pi = (j & 15) + 16 * (j >> 5);
            if (j & 16) {
                As2[kq + 0][pi].y = v.x; As2[kq + 1][pi].y = v.y;
                As2[kq + 2][pi].y = v.z; As2[kq + 3][pi].y = v.w;
            } else {
                As2[kq + 0][pi].x = v.x; As2[kq + 1][pi].x = v.y;
                As2[kq + 2][pi].x = v.z; As2[kq + 3][pi].x = v.w;
            }
        }
        __syncthreads();
        #pragma unroll 8
        for (int kk = 0; kk < 32; kk++) {
            ull av[4];
            #pragma unroll
            for (int q = 0; q < 4; q++)
                av[q] = *(const ull*)&As2[kk][tx + 16 * q];
            #pragma unroll
            for (int ii = 0; ii < 8; ii++) {
                float xv = Xs[ty * 8 + ii][kk];
                ull xx;
                asm("mov.b64 %0, {%1, %1};" : "=l"(xx) : "f"(xv));
                #pragma unroll
                for (int q = 0; q < 4; q++)
                    asm("fma.rn.f32x2 %0, %1, %2, %0;"
                        : "+l"(acc[ii][q]) : "l"(xx), "l"(av[q]));
            }
        }
        __syncthreads();
    }
    #pragma unroll
    for (int ii = 0; ii < 8; ii++) {
        int gi = ib + ty * 8 + ii;
        if (gi < M) {
            #pragma unroll
            for (int q = 0; q < 4; q++) {
                float lo, hi;
                asm("mov.b64 {%0, %1}, %2;" : "=f"(lo), "=f"(hi) : "l"(acc[ii][q]));
                C[(size_t)gi * N + jb + tx + 32 * q] = lo;
                C[(size_t)gi * N + jb + tx + 32 * q + 16] = hi;
            }
        }
    }
}

// ---------------- layer-1 edge pass: warp per (dir, edge), both heads ----------------
__global__ void edge_pass1(const int* __restrict__ el, const int* __restrict__ eln,
                           const int* __restrict__ etn,
                           const float* __restrict__ a2_in, const float* __restrict__ a2_out) {
    int dir = blockIdx.y;
    int e = blockIdx.x * 8 + (threadIdx.x >> 5);
    int lane = threadIdx.x & 31;
    int h = lane >> 4;
    int jj = 4 * (lane & 15);
    int i0, i1;
    float4 q;
    if (e < E_REAL) {
        i0 = el[e]; i1 = el[E_REAL + e];
        q = *(const float4*)&g_Q1all[(size_t)e * 256 + dir * 128 + h * 64 + jj];
    } else {
        int en = e - E_REAL;
        i0 = eln[en]; i1 = eln[E_NHOP + en];
        int t0 = etn[2 * en], t1 = etn[2 * en + 1];
        float4 qa = *(const float4*)&g_R1proj[t0 * 256 + dir * 128 + h * 64 + jj];
        float4 qb = *(const float4*)&g_R1proj[t1 * 256 + dir * 128 + h * 64 + jj];
        q.x = qa.x + qb.x; q.y = qa.y + qb.y; q.z = qa.z + qb.z; q.w = qa.w + qb.w;
    }
    int src = dir ? i1 : i0;
    int dst = dir ? i0 : i1;
    float4 p = *(const float4*)&g_P1all[(size_t)src * 512 + dir * 256 + h * 64 + jj];
    float4 d = *(const float4*)&g_P1all[(size_t)dst * 512 + dir * 256 + 128 + h * 64 + jj];
    float m0 = p.x + d.x + q.x;
    float m1 = p.y + d.y + q.y;
    float m2 = p.z + d.z + q.z;
    float m3 = p.w + d.w + q.w;
    const float* a2 = (dir ? a2_out : a2_in) + h * 64 + jj;
    float part = m0 * a2[0] + m1 * a2[1] + m2 * a2[2] + m3 * a2[3];
    #pragma unroll
    for (int o = 8; o; o >>= 1) part += __shfl_xor_sync(0xffffffffu, part, o);
    float lk = part > 0.f ? part : ALPHA * part;
    float ev = expf(-lk);
    float* hp = &g_hp1[dir][(size_t)src * 128 + h * 64 + jj];
    RED4(hp, ev * m0, ev * m1, ev * m2, ev * m3);
    if ((lane & 15) == 0) atomicAdd(&g_rowsum1[dir * 2 + h][src], ev);
}

// ---------------- normalize + elu -> x_s ----------------
__global__ void norm1() {
    int dir = blockIdx.y;
    int idx = blockIdx.x * 256 + threadIdx.x;
    if (idx >= N_NODES * 128) return;
    int i = idx >> 7, kk = idx & 127;
    int h = kk >> 6;
    float rs = g_rowsum1[dir * 2 + h][i];
    float v = g_hp1[dir][idx];
    v = (rs > 0.f) ? v / rs : 0.f;
    v = (v > 0.f) ? v : expm1f(v);
    g_xs[dir][idx] = v;
}

// ---------------- layer-2 edge pass ----------------
__global__ void edge_pass2(const int* __restrict__ el, const int* __restrict__ eln,
                           const int* __restrict__ et, const int* __restrict__ etn,
                           const float* __restrict__ a2_o) {
    int dir = blockIdx.y;
    int e = blockIdx.x * 8 + (threadIdx.x >> 5);
    int lane = threadIdx.x & 31;
    int i0, i1;
    float q0, q1, q2, q3;
    if (e < E_REAL) {
        i0 = el[e]; i1 = el[E_REAL + e];
        int ty = et[e];
        float4 qv = *(const float4*)&g_R2proj[ty * 128 + 4 * lane];
        q0 = qv.x; q1 = qv.y; q2 = qv.z; q3 = qv.w;
    } else {
        int en = e - E_REAL;
        i0 = eln[en]; i1 = eln[E_NHOP + en];
        int t0 = etn[2 * en], t1 = etn[2 * en + 1];
        float4 qa = *(const float4*)&g_R2proj[t0 * 128 + 4 * lane];
        float4 qb = *(const float4*)&g_R2proj[t1 * 128 + 4 * lane];
        q0 = qa.x + qb.x; q1 = qa.y + qb.y; q2 = qa.z + qb.z; q3 = qa.w + qb.w;
    }
    int seg = dir ? i1 : i0;
    int nbr = dir ? i0 : i1;
    float4 pv = *(const float4*)&g_P2all[dir][(size_t)seg * 256 + 4 * lane];
    float4 dv = *(const float4*)&g_P2all[dir][(size_t)nbr * 256 + 128 + 4 * lane];
    float m0 = pv.x + dv.x + q0;
    float m1 = pv.y + dv.y + q1;
    float m2 = pv.z + dv.z + q2;
    float m3 = pv.w + dv.w + q3;
    float4 av = *(const float4*)&a2_o[4 * lane];
    float part = m0 * av.x + m1 * av.y + m2 * av.z + m3 * av.w;
    #pragma unroll
    for (int o = 16; o; o >>= 1) part += __shfl_xor_sync(0xffffffffu, part, o);
    float lk = part > 0.f ? part : ALPHA * part;
    float ev = expf(-lk);
    float* hp = &g_hp2[dir][(size_t)seg * 128 + 4 * lane];
    RED4(hp, ev * m0, ev * m1, ev * m2, ev * m3);
    if (lane == 0) atomicAdd(&g_rowsum2[dir][seg], ev);
}

// ---------------- layer-2 normalize + elu + attention scores ----------------
__global__ void node_final1(const float* __restrict__ We, const float* __restrict__ be,
                            const float* __restrict__ qe) {
    int xs = blockIdx.y;
    int w = threadIdx.x >> 5;
    int lane = threadIdx.x & 31;
    int node = blockIdx.x * 8 + w;
    if (node >= N_NODES) return;
    __shared__ float ysm[8][128];
    float rs = g_rowsum2[xs][node];
    float inv = (rs > 0.f) ? 1.f / rs : 0.f;
    #pragma unroll
    for (int u = 0; u < 4; u++) {
        int k = 4 * lane + u;
        float v = g_hp2[xs][(size_t)node * 128 + k] * inv;
        v = (v > 0.f) ? v : expm1f(v);
        ysm[w][k] = v;
        g_y[xs][(size_t)node * 128 + k] = v;
    }
    __syncwarp();
    float wp = 0.f;
    #pragma unroll
    for (int half = 0; half < 2; half++) {
        int j = lane + 32 * half;
        float acc = be[j];
        #pragma unroll 8
        for (int k = 0; k < 128; k++) acc += ysm[w][k] * We[k * 64 + j];
        wp += tanhf(acc) * qe[j];
    }
    #pragma unroll
    for (int o = 16; o; o >>= 1) wp += __shfl_xor_sync(0xffffffffu, wp, o);
    if (lane == 0) atomicAdd(&g_wsum[xs], wp);
}

// ---------------- beta + combine (fused) ----------------
__global__ void combine(float* __restrict__ out) {
    float m0 = g_wsum[0] / (float)N_NODES;
    float m1 = g_wsum[1] / (float)N_NODES;
    float mx = fmaxf(m0, m1);
    float e0 = expf(m0 - mx), e1 = expf(m1 - mx);
    float b0 = e0 / (e0 + e1), b1 = e1 / (e0 + e1);
    size_t i = (size_t)blockIdx.x * 256 + threadIdx.x;
    if (i >= (size_t)N_NODES * OUTF) return;
    out[i] = b0 * g_y[0][i] + b1 * g_y[1][i];
}

// ---------------- launch ----------------
extern "C" void kernel_launch(void* const* d_in, const int* in_sizes, int n_in,
                              void* d_out, int out_size) {
    const float* ent   = (const float*)d_in[0];
    const float* rel   = (const float*)d_in[1];
    const int*   el    = (const int*)d_in[2];
    const int*   et    = (const int*)d_in[3];
    const float* eemb  = (const float*)d_in[4];
    const int*   eln   = (const int*)d_in[5];
    const int*   etn   = (const int*)d_in[6];
    const float* a_in  = (const float*)d_in[7];
    const float* a2_in = (const float*)d_in[8];
    const float* a_out = (const float*)d_in[9];
    const float* a2_out= (const float*)d_in[10];
    const float* a_o   = (const float*)d_in[11];
    const float* a2_o  = (const float*)d_in[12];
    const float* W     = (const float*)d_in[13];
    const float* We    = (const float*)d_in[14];
    const float* be    = (const float*)d_in[15];
    const float* qe    = (const float*)d_in[16];
    float* out = (float*)d_out;

    float *p1 = 0, *q1 = 0, *xsb = 0, *p2 = 0, *wp1 = 0, *wpq = 0, *wp2 = 0;
    cudaGetSymbolAddress((void**)&p1, g_P1all);
    cudaGetSymbolAddress((void**)&q1, g_Q1all);
    cudaGetSymbolAddress((void**)&xsb, g_xs);
    cudaGetSymbolAddress((void**)&p2, g_P2all);
    cudaGetSymbolAddress((void**)&wp1, g_Wp1);
    cudaGetSymbolAddress((void**)&wpq, g_WpQ);
    cudaGetSymbolAddress((void**)&wp2, g_Wp2);

    prep<<<ZB + 28, 256>>>(a_in, a_out, a_o, rel, W, out);

    gemm_f32x2<<<dim3((N_NODES + 127) / 128, 4), 256>>>(ent, wp1, p1, N_NODES, 512, 64);
    gemm_f32x2<<<dim3((E_REAL + 127) / 128, 2), 256>>>(eemb, wpq, q1, E_REAL, 256, 64);

    edge_pass1<<<dim3(E_ALL / 8, 2), 256>>>(el, eln, etn, a2_in, a2_out);
    norm1<<<dim3((N_NODES * 128 + 255) / 256, 2), 256>>>();

    for (int xs = 0; xs < 2; xs++)
        gemm_f32x2<<<dim3((N_NODES + 127) / 128, 2), 256>>>(
            xsb + (size_t)xs * N_NODES * 128, wp2,
            p2 + (size_t)xs * N_NODES * 256, N_NODES, 256, 128);

    edge_pass2<<<dim3(E_ALL / 8, 2), 256>>>(el, eln, et, etn, a2_o);
    node_final1<<<dim3((N_NODES + 7) / 8, 2), 256>>>(We, be, qe);
    combine<<<(N_NODES * OUTF + 255) / 256, 256>>>(out);
}

// round 7
// speedup vs baseline: 1.2488x; 1.1957x over previous
#include <cuda_runtime.h>
#include <math.h>

#define N_NODES 50000
#define NFEAT   64
#define NHID    64
#define E_REAL  200000
#define E_NHOP  40000
#define E_ALL   240000
#define N_REL   200
#define OUTF    128
#define ALPHA   0.2f

typedef unsigned long long ull;

// ---------------- device scratch (R2 layouts) ----------------
// P1 layout: [i][c*128 + role*64 + j], c = dir*2 + h
__device__ __align__(16) float g_P1all[(size_t)N_NODES * 512];
// Q1 layout: [e][c*64 + j]
__device__ __align__(16) float g_Q1all[(size_t)E_REAL * 256];
__device__ __align__(16) float g_R1proj[4][N_REL * 64];
__device__ __align__(16) float g_rel2[N_REL * OUTF];
__device__ __align__(16) float g_R2proj[N_REL * OUTF];
__device__ float g_rowsum1[4][N_NODES];
__device__ __align__(16) float g_hp1[4][(size_t)N_NODES * 64];
__device__ __align__(16) float g_xs[2][(size_t)N_NODES * OUTF];
__device__ __align__(16) float g_P2all[2][(size_t)N_NODES * 256];  // [xs][i][role*128 + j]
__device__ float g_rowsum2[2][N_NODES];
__device__ __align__(16) float g_hp2[2][(size_t)N_NODES * OUTF];
__device__ __align__(16) float g_y[2][(size_t)N_NODES * OUTF];
__device__ float g_wsum[2];
// packed weights (row-major [n][K])
__device__ __align__(16) float g_Wp1[512 * 64];
__device__ __align__(16) float g_WpQ[256 * 64];
__device__ __align__(16) float g_Wp2[256 * 128];
// factorized attention scalars
__device__ __align__(16) float g_S1[(size_t)N_NODES * 8];   // [i*8 + c*2 + role]
__device__ __align__(16) float g_SQ1[(size_t)E_REAL * 4];   // [e*4 + c]
__device__ __align__(16) float g_Sr1[N_REL * 4];            // [r*4 + c]
__device__ __align__(16) float g_S2[2][(size_t)N_NODES * 4];// [xs][i*4 + blk]
__device__ float g_Srel2[N_REL];
// per-column dot weights aligned with GEMM outputs
__device__ __align__(16) float g_a2cat1[512];
__device__ __align__(16) float g_a2catQ[256];
__device__ __align__(16) float g_a2cat2[256];

#define RED2(ptr, a, b) \
    asm volatile("red.global.add.v2.f32 [%0], {%1, %2};" :: "l"(ptr), "f"(a), "f"(b) : "memory")
#define RED4(ptr, a, b, c, d) \
    asm volatile("red.global.add.v4.f32 [%0], {%1, %2, %3, %4};" :: "l"(ptr), "f"(a), "f"(b), "f"(c), "f"(d) : "memory")

// ---------------- zero accumulators (R2) ----------------
__global__ void zero_accum() {
    size_t stride = (size_t)gridDim.x * blockDim.x;
    size_t i0 = (size_t)blockIdx.x * blockDim.x + threadIdx.x;
    float* hp1 = &g_hp1[0][0];
    float* hp2 = &g_hp2[0][0];
    for (size_t i = i0; i < (size_t)4 * N_NODES * 64; i += stride) hp1[i] = 0.f;
    for (size_t i = i0; i < (size_t)2 * N_NODES * OUTF; i += stride) hp2[i] = 0.f;
    float* rs1 = &g_rowsum1[0][0];
    float* rs2 = &g_rowsum2[0][0];
    for (size_t i = i0; i < (size_t)4 * N_NODES; i += stride) rs1[i] = 0.f;
    for (size_t i = i0; i < (size_t)2 * N_NODES; i += stride) rs2[i] = 0.f;
    if (i0 < 2) g_wsum[i0] = 0.f;
}

// ---------------- weight packing (1025 blocks: fixes Wp2 row-255 bug) ----------------
__global__ void pack_all(const float* __restrict__ a_in, const float* __restrict__ a_out,
                         const float* __restrict__ a_o,
                         const float* __restrict__ a2_in, const float* __restrict__ a2_out,
                         const float* __restrict__ a2_o) {
    int r = blockIdx.x;
    int k = threadIdx.x;  // 128
    if (r < 512) {
        if (k < 64) {
            int c = r >> 7, rem = r & 127, role = rem >> 6, j = rem & 63;
            const float* A = ((c >> 1) ? a_out : a_in) + (size_t)(c & 1) * 64 * 192;
            g_Wp1[r * 64 + k] = A[j * 192 + role * 64 + k];
        }
    } else if (r < 768) {
        if (k < 64) {
            int rr = r - 512;
            int c = rr >> 6, j = rr & 63;
            const float* A = ((c >> 1) ? a_out : a_in) + (size_t)(c & 1) * 64 * 192;
            g_WpQ[rr * 64 + k] = A[j * 192 + 128 + k];
        }
    } else if (r < 1024) {
        int rr = r - 768;   // 0..255 — ALL 256 rows packed now
        int role = rr >> 7, j = rr & 127;
        g_Wp2[rr * 128 + k] = a_o[j * 384 + role * 128 + k];
    } else {
        // a2cat tables (block 1024)
        for (int n = k; n < 512; n += 128) {
            int c = n >> 7, j = n & 63;
            g_a2cat1[n] = ((c >> 1) ? a2_out : a2_in)[(c & 1) * 64 + j];
        }
        for (int n = k; n < 256; n += 128) {
            int c = n >> 6, j = n & 63;
            g_a2catQ[n] = ((c >> 1) ? a2_out : a2_in)[(c & 1) * 64 + j];
        }
        for (int n = k; n < 256; n += 128)
            g_a2cat2[n] = a2_o[n & 127];
    }
}

// ---------------- small relation-table kernels ----------------
__global__ void k_rel2(const float* __restrict__ rel, const float* __restrict__ W,
                       float* __restrict__ out_tail) {
    int r = blockIdx.x, j = threadIdx.x;
    float acc = 0.f;
    #pragma unroll
    for (int k = 0; k < 64; k++) acc += rel[r * 64 + k] * W[k * 128 + j];
    g_rel2[r * 128 + j] = acc;
    out_tail[(size_t)N_NODES * OUTF + r * 128 + j] = acc;
}

// R2proj + Srel2 (dot with a2_o)
__global__ void k_r2proj(const float* __restrict__ a_o, const float* __restrict__ a2_o) {
    int r = blockIdx.x, j = threadIdx.x;
    float acc = 0.f;
    #pragma unroll
    for (int k = 0; k < 128; k++) acc += g_rel2[r * 128 + k] * a_o[j * 384 + 256 + k];
    g_R2proj[r * 128 + j] = acc;
    float part = acc * a2_o[j];
    #pragma unroll
    for (int o = 16; o; o >>= 1) part += __shfl_xor_sync(0xffffffffu, part, o);
    __shared__ float ws[4];
    if ((j & 31) == 0) ws[j >> 5] = part;
    __syncthreads();
    if (j == 0) g_Srel2[r] = ws[0] + ws[1] + ws[2] + ws[3];
}

// R1proj + Sr1 (per-combo dot with a2)
__global__ void k_r1proj(const float* __restrict__ rel, const float* __restrict__ a_in,
                         const float* __restrict__ a_out,
                         const float* __restrict__ a2_in, const float* __restrict__ a2_out) {
    int r = blockIdx.x;
    int t = threadIdx.x;
    int c = t >> 6;
    int j = t & 63;
    const float* A = ((c >> 1) ? a_out : a_in) + (size_t)(c & 1) * 64 * 192;
    float acc = 0.f;
    #pragma unroll
    for (int k = 0; k < 64; k++) acc += rel[r * 64 + k] * A[j * 192 + 128 + k];
    g_R1proj[c][r * 64 + j] = acc;
    float part = acc * ((c >> 1) ? a2_out : a2_in)[(c & 1) * 64 + j];
    #pragma unroll
    for (int o = 16; o; o >>= 1) part += __shfl_xor_sync(0xffffffffu, part, o);
    __shared__ float ws[8];
    if ((t & 31) == 0) ws[t >> 5] = part;
    __syncthreads();
    if (t < 4) g_Sr1[r * 4 + t] = ws[2 * t] + ws[2 * t + 1];
}

// ---------------- f32x2 packed GEMM (R2) + score-dot epilogue ----------------
// C[i][jb+j] = sum_k X[i][k] * Wp[(jb+j)][k]; sOut[i*(N/64) + colblk] = row-dot with a2cat per 64-col block
__global__ void gemm_f32x2(const float* __restrict__ X,
                           const float* __restrict__ Wp,
                           float* __restrict__ C,
                           const float* __restrict__ a2cat,
                           float* __restrict__ sOut,
                           int M, int N, int K) {
    __shared__ float Xs[128][33];
    __shared__ float2 As2[32][65];
    int t = threadIdx.x;
    int tx = t & 15, ty = t >> 4;
    int ib = blockIdx.x * 128;
    int jb = blockIdx.y * 128;
    ull acc[8][4];
    #pragma unroll
    for (int ii = 0; ii < 8; ii++)
        #pragma unroll
        for (int q = 0; q < 4; q++) acc[ii][q] = 0ull;

    for (int kc = 0; kc < K; kc += 32) {
        #pragma unroll
        for (int p = t; p < 1024; p += 256) {
            int i = p >> 3, kq = (p & 7) * 4;
            int gi = ib + i;
            float4 v = make_float4(0.f, 0.f, 0.f, 0.f);
            if (gi < M) v = *(const float4*)&X[(size_t)gi * K + kc + kq];
            Xs[i][kq + 0] = v.x; Xs[i][kq + 1] = v.y;
            Xs[i][kq + 2] = v.z; Xs[i][kq + 3] = v.w;
        }
        #pragma unroll
        for (int p = t; p < 1024; p += 256) {
            int j = p >> 3, kq = (p & 7) * 4;
            float4 v = *(const float4*)&Wp[(size_t)(jb + j) * K + kc + kq];
            int pi = (j & 15) + 16 * (j >> 5);
            if (j & 16) {
                As2[kq + 0][pi].y = v.x; As2[kq + 1][pi].y = v.y;
                As2[kq + 2][pi].y = v.z; As2[kq + 3][pi].y = v.w;
            } else {
                As2[kq + 0][pi].x = v.x; As2[kq + 1][pi].x = v.y;
                As2[kq + 2][pi].x = v.z; As2[kq + 3][pi].x = v.w;
            }
        }
        __syncthreads();
        #pragma unroll 8
        for (int kk = 0; kk < 32; kk++) {
            ull av[4];
            #pragma unroll
            for (int q = 0; q < 4; q++)
                av[q] = *(const ull*)&As2[kk][tx + 16 * q];
            #pragma unroll
            for (int ii = 0; ii < 8; ii++) {
                float xv = Xs[ty * 8 + ii][kk];
                ull xx;
                asm("mov.b64 %0, {%1, %1};" : "=l"(xx) : "f"(xv));
                #pragma unroll
                for (int q = 0; q < 4; q++)
                    asm("fma.rn.f32x2 %0, %1, %2, %0;"
                        : "+l"(acc[ii][q]) : "l"(xx), "l"(av[q]));
            }
        }
        __syncthreads();
    }
    int nBlk = N >> 6;
    float w[8];
    #pragma unroll
    for (int q = 0; q < 4; q++) {
        w[2 * q]     = a2cat[jb + tx + 32 * q];
        w[2 * q + 1] = a2cat[jb + tx + 32 * q + 16];
    }
    #pragma unroll
    for (int ii = 0; ii < 8; ii++) {
        int gi = ib + ty * 8 + ii;
        float lo[4], hi[4];
        #pragma unroll
        for (int q = 0; q < 4; q++)
            asm("mov.b64 {%0, %1}, %2;" : "=f"(lo[q]), "=f"(hi[q]) : "l"(acc[ii][q]));
        if (gi < M) {
            #pragma unroll
            for (int q = 0; q < 4; q++) {
                C[(size_t)gi * N + jb + tx + 32 * q] = lo[q];
                C[(size_t)gi * N + jb + tx + 32 * q + 16] = hi[q];
            }
        }
        float s0 = lo[0] * w[0] + hi[0] * w[1] + lo[1] * w[2] + hi[1] * w[3];
        float s1 = lo[2] * w[4] + hi[2] * w[5] + lo[3] * w[6] + hi[3] * w[7];
        #pragma unroll
        for (int o = 8; o; o >>= 1) {
            s0 += __shfl_xor_sync(0xffffffffu, s0, o);
            s1 += __shfl_xor_sync(0xffffffffu, s1, o);
        }
        if (tx == 0 && gi < M) {
            size_t base = (size_t)gi * nBlk + (jb >> 6);
            sOut[base] = s0;
            sOut[base + 1] = s1;
        }
    }
}

// ---------------- layer-1 edge pass: warp per (combo, edge), factorized score ----------------
__global__ void edge_pass1(const int* __restrict__ el, const int* __restrict__ eln,
                           const int* __restrict__ etn) {
    int c = blockIdx.y;
    int e = blockIdx.x * 8 + (threadIdx.x >> 5);
    if (e >= E_ALL) return;
    int lane = threadIdx.x & 31;
    int dir = c >> 1;
    int i0, i1;
    float qx, qy, sq;
    if (e < E_REAL) {
        i0 = el[e]; i1 = el[E_REAL + e];
        float2 q2 = *(const float2*)&g_Q1all[(size_t)e * 256 + c * 64 + 2 * lane];
        qx = q2.x; qy = q2.y;
        sq = g_SQ1[(size_t)e * 4 + c];
    } else {
        int en = e - E_REAL;
        i0 = eln[en]; i1 = eln[E_NHOP + en];
        int t0 = etn[2 * en], t1 = etn[2 * en + 1];
        float2 qa = *(const float2*)&g_R1proj[c][t0 * 64 + 2 * lane];
        float2 qb = *(const float2*)&g_R1proj[c][t1 * 64 + 2 * lane];
        qx = qa.x + qb.x; qy = qa.y + qb.y;
        sq = g_Sr1[t0 * 4 + c] + g_Sr1[t1 * 4 + c];
    }
    int src = dir ? i1 : i0;   // segment node (edge[0] of this direction)
    int dst = dir ? i0 : i1;
    // score = p_src.a2 + p_dst.a2 + q.a2 (precomputed scalars, broadcast loads)
    float score = g_S1[(size_t)src * 8 + c * 2] + g_S1[(size_t)dst * 8 + c * 2 + 1] + sq;
    float lk = score > 0.f ? score : ALPHA * score;
    float ev = expf(-lk);
    // scatter only d + q part; rowsum*p_src added in norm1
    float2 d = *(const float2*)&g_P1all[(size_t)dst * 512 + c * 128 + 64 + 2 * lane];
    float* hp = &g_hp1[c][(size_t)src * 64 + 2 * lane];
    RED2(hp, ev * (d.x + qx), ev * (d.y + qy));
    if (lane == 0) atomicAdd(&g_rowsum1[c][src], ev);
}

// ---------------- normalize (+ fold back p_src) + elu -> x_s ----------------
__global__ void norm1() {
    int c = blockIdx.y;
    int idx = blockIdx.x * 256 + threadIdx.x;
    if (idx >= N_NODES * 64) return;
    int i = idx >> 6, k = idx & 63;
    float rs = g_rowsum1[c][i];
    float v = g_hp1[c][idx];
    v = (rs > 0.f) ? v / rs + g_P1all[(size_t)i * 512 + c * 128 + k] : 0.f;
    v = (v > 0.f) ? v : expm1f(v);
    int dir = c >> 1, h = c & 1;
    g_xs[dir][(size_t)i * 128 + h * 64 + k] = v;
}

// ---------------- layer-2 edge pass: factorized score ----------------
__global__ void edge_pass2(const int* __restrict__ el, const int* __restrict__ eln,
                           const int* __restrict__ et, const int* __restrict__ etn) {
    int dir = blockIdx.y;
    int e = blockIdx.x * 8 + (threadIdx.x >> 5);
    if (e >= E_ALL) return;
    int lane = threadIdx.x & 31;
    int i0, i1;
    float q0, q1, q2, q3, sq;
    if (e < E_REAL) {
        i0 = el[e]; i1 = el[E_REAL + e];
        int ty = et[e];
        float4 qv = *(const float4*)&g_R2proj[ty * 128 + 4 * lane];
        q0 = qv.x; q1 = qv.y; q2 = qv.z; q3 = qv.w;
        sq = g_Srel2[ty];
    } else {
        int en = e - E_REAL;
        i0 = eln[en]; i1 = eln[E_NHOP + en];
        int t0 = etn[2 * en], t1 = etn[2 * en + 1];
        float4 qa = *(const float4*)&g_R2proj[t0 * 128 + 4 * lane];
        float4 qb = *(const float4*)&g_R2proj[t1 * 128 + 4 * lane];
        q0 = qa.x + qb.x; q1 = qa.y + qb.y; q2 = qa.z + qb.z; q3 = qa.w + qb.w;
        sq = g_Srel2[t0] + g_Srel2[t1];
    }
    int seg = dir ? i1 : i0;
    int nbr = dir ? i0 : i1;
    float4 sA = *(const float4*)&g_S2[dir][(size_t)seg * 4];  // ss = x+y (role0 blocks)
    float4 sB = *(const float4*)&g_S2[dir][(size_t)nbr * 4];  // sd = z+w (role1 blocks)
    float score = sA.x + sA.y + sB.z + sB.w + sq;
    float lk = score > 0.f ? score : ALPHA * score;
    float ev = expf(-lk);
    float4 dv = *(const float4*)&g_P2all[dir][(size_t)nbr * 256 + 128 + 4 * lane];
    float* hp = &g_hp2[dir][(size_t)seg * 128 + 4 * lane];
    RED4(hp, ev * (dv.x + q0), ev * (dv.y + q1), ev * (dv.z + q2), ev * (dv.w + q3));
    if (lane == 0) atomicAdd(&g_rowsum2[dir][seg], ev);
}

// ---------------- layer-2 normalize (+ fold p_seg) + elu + attention scores ----------------
__global__ void node_final1(const float* __restrict__ We, const float* __restrict__ be,
                            const float* __restrict__ qe) {
    int xs = blockIdx.y;
    int w = threadIdx.x >> 5;
    int lane = threadIdx.x & 31;
    int node = blockIdx.x * 8 + w;
    if (node >= N_NODES) return;
    __shared__ float ysm[8][128];
    float rs = g_rowsum2[xs][node];
    float inv = (rs > 0.f) ? 1.f / rs : 0.f;
    #pragma unroll
    for (int u = 0; u < 4; u++) {
        int k = 4 * lane + u;
        float v = (rs > 0.f)
            ? g_hp2[xs][(size_t)node * 128 + k] * inv + g_P2all[xs][(size_t)node * 256 + k]
            : 0.f;
        v = (v > 0.f) ? v : expm1f(v);
        ysm[w][k] = v;
        g_y[xs][(size_t)node * 128 + k] = v;
    }
    __syncwarp();
    float wp = 0.f;
    #pragma unroll
    for (int half = 0; half < 2; half++) {
        int j = lane + 32 * half;
        float acc = be[j];
        #pragma unroll 8
        for (int k = 0; k < 128; k++) acc += ysm[w][k] * We[k * 64 + j];
        wp += tanhf(acc) * qe[j];
    }
    #pragma unroll
    for (int o = 16; o; o >>= 1) wp += __shfl_xor_sync(0xffffffffu, wp, o);
    if (lane == 0) atomicAdd(&g_wsum[xs], wp);
}

// ---------------- beta + combine (fused) ----------------
__global__ void combine(float* __restrict__ out) {
    float m0 = g_wsum[0] / (float)N_NODES;
    float m1 = g_wsum[1] / (float)N_NODES;
    float mx = fmaxf(m0, m1);
    float e0 = expf(m0 - mx), e1 = expf(m1 - mx);
    float b0 = e0 / (e0 + e1), b1 = e1 / (e0 + e1);
    size_t i = (size_t)blockIdx.x * 256 + threadIdx.x;
    if (i >= (size_t)N_NODES * OUTF) return;
    out[i] = b0 * g_y[0][i] + b1 * g_y[1][i];
}

// ---------------- launch ----------------
extern "C" void kernel_launch(void* const* d_in, const int* in_sizes, int n_in,
                              void* d_out, int out_size) {
    const float* ent   = (const float*)d_in[0];
    const float* rel   = (const float*)d_in[1];
    const int*   el    = (const int*)d_in[2];
    const int*   et    = (const int*)d_in[3];
    const float* eemb  = (const float*)d_in[4];
    const int*   eln   = (const int*)d_in[5];
    const int*   etn   = (const int*)d_in[6];
    const float* a_in  = (const float*)d_in[7];
    const float* a2_in = (const float*)d_in[8];
    const float* a_out = (const float*)d_in[9];
    const float* a2_out= (const float*)d_in[10];
    const float* a_o   = (const float*)d_in[11];
    const float* a2_o  = (const float*)d_in[12];
    const float* W     = (const float*)d_in[13];
    const float* We    = (const float*)d_in[14];
    const float* be    = (const float*)d_in[15];
    const float* qe    = (const float*)d_in[16];
    float* out = (float*)d_out;

    float *p1 = 0, *q1 = 0, *xsb = 0, *p2 = 0, *wp1 = 0, *wpq = 0, *wp2 = 0;
    float *a2c1 = 0, *a2cq = 0, *a2c2 = 0, *s1 = 0, *sq1 = 0, *s2 = 0;
    cudaGetSymbolAddress((void**)&p1, g_P1all);
    cudaGetSymbolAddress((void**)&q1, g_Q1all);
    cudaGetSymbolAddress((void**)&xsb, g_xs);
    cudaGetSymbolAddress((void**)&p2, g_P2all);
    cudaGetSymbolAddress((void**)&wp1, g_Wp1);
    cudaGetSymbolAddress((void**)&wpq, g_WpQ);
    cudaGetSymbolAddress((void**)&wp2, g_Wp2);
    cudaGetSymbolAddress((void**)&a2c1, g_a2cat1);
    cudaGetSymbolAddress((void**)&a2cq, g_a2catQ);
    cudaGetSymbolAddress((void**)&a2c2, g_a2cat2);
    cudaGetSymbolAddress((void**)&s1, g_S1);
    cudaGetSymbolAddress((void**)&sq1, g_SQ1);
    cudaGetSymbolAddress((void**)&s2, g_S2);

    zero_accum<<<4096, 256>>>();
    pack_all<<<1025, 128>>>(a_in, a_out, a_o, a2_in, a2_out, a2_o);
    k_rel2<<<200, 128>>>(rel, W, out);
    k_r2proj<<<200, 128>>>(a_o, a2_o);
    k_r1proj<<<200, 256>>>(rel, a_in, a_out, a2_in, a2_out);

    // layer-1 projections with fused score-dot epilogues
    gemm_f32x2<<<dim3((N_NODES + 127) / 128, 4), 256>>>(ent, wp1, p1, a2c1, s1,
                                                        N_NODES, 512, 64);
    gemm_f32x2<<<dim3((E_REAL + 127) / 128, 2), 256>>>(eemb, wpq, q1, a2cq, sq1,
                                                       E_REAL, 256, 64);

    edge_pass1<<<dim3(E_ALL / 8, 4), 256>>>(el, eln, etn);
    norm1<<<dim3((N_NODES * 64 + 255) / 256, 4), 256>>>();

    // layer-2 projections
    for (int xs = 0; xs < 2; xs++)
        gemm_f32x2<<<dim3((N_NODES + 127) / 128, 2), 256>>>(
            xsb + (size_t)xs * N_NODES * 128, wp2,
            p2 + (size_t)xs * N_NODES * 256,
            a2c2, s2 + (size_t)xs * N_NODES * 4,
            N_NODES, 256, 128);

    edge_pass2<<<dim3(E_ALL / 8, 2), 256>>>(el, eln, et, etn);
    node_final1<<<dim3((N_NODES + 7) / 8, 2), 256>>>(We, be, qe);
    combine<<<(N_NODES * OUTF + 255) / 256, 256>>>(out);
}

// round 8
// speedup vs baseline: 1.4843x; 1.1886x over previous
#include <cuda_runtime.h>
#include <math.h>

#define N_NODES 50000
#define NFEAT   64
#define NHID    64
#define E_REAL  200000
#define E_NHOP  40000
#define E_ALL   240000
#define N_REL   200
#define OUTF    128
#define ALPHA   0.2f

typedef unsigned long long ull;

// ---------------- device scratch ----------------
__device__ __align__(16) float g_P1all[(size_t)N_NODES * 512];     // [i][c*128 + role*64 + j]
__device__ __align__(16) float g_Q1all[(size_t)E_REAL * 256];      // [e][c*64 + j]
__device__ __align__(16) float g_R1proj[4][N_REL * 64];
__device__ __align__(16) float g_R2proj[N_REL * OUTF];
__device__ float g_rowsum1[4][N_NODES];
__device__ __align__(16) float g_hp1[4][(size_t)N_NODES * 64];
__device__ __align__(16) float g_xs[2][(size_t)N_NODES * OUTF];
__device__ __align__(16) float g_P2all[2][(size_t)N_NODES * 256];  // [xs][i][role*128 + j]
__device__ float g_rowsum2[2][N_NODES];
__device__ __align__(16) float g_hp2[2][(size_t)N_NODES * OUTF];
__device__ __align__(16) float g_y[2][(size_t)N_NODES * OUTF];
__device__ __align__(16) float g_tw[(size_t)2 * N_NODES * 128];    // tanh-input GEMM out
__device__ float g_wsum[2];
// packed weights (row-major [n][K])
__device__ __align__(16) float g_Wp1[512 * 64];
__device__ __align__(16) float g_WpQ[256 * 64];
__device__ __align__(16) float g_Wp2[256 * 128];
__device__ __align__(16) float g_WeP[128 * 128];                   // [j][k], rows 64+ zero
// factorized attention scalars
__device__ __align__(16) float g_S1[(size_t)N_NODES * 8];
__device__ __align__(16) float g_SQ1[(size_t)E_REAL * 4];
__device__ __align__(16) float g_Sr1[N_REL * 4];
__device__ __align__(16) float g_S2[2][(size_t)N_NODES * 4];
__device__ float g_Srel2[N_REL];
__device__ __align__(16) float g_Sdummy[(size_t)2 * N_NODES * 2];
// per-column dot weights aligned with GEMM outputs
__device__ __align__(16) float g_a2cat1[512];
__device__ __align__(16) float g_a2catQ[256];
__device__ __align__(16) float g_a2cat2[256];

#define RED2(ptr, a, b) \
    asm volatile("red.global.add.v2.f32 [%0], {%1, %2};" :: "l"(ptr), "f"(a), "f"(b) : "memory")
#define RED4(ptr, a, b, c, d) \
    asm volatile("red.global.add.v4.f32 [%0], {%1, %2, %3, %4};" :: "l"(ptr), "f"(a), "f"(b), "f"(c), "f"(d) : "memory")

// ---------------- fused setup: zero + pack + all relation tables ----------------
// blocks: [0,512) zero | 512-515 Wp1 | 516-517 WpQ | 518-521 Wp2 | 522-525 WeP
//         | 526 a2cat | [527, 727) relation blocks (r = b-527)
__global__ void setup(const float* __restrict__ a_in, const float* __restrict__ a_out,
                      const float* __restrict__ a_o,
                      const float* __restrict__ a2_in, const float* __restrict__ a2_out,
                      const float* __restrict__ a2_o,
                      const float* __restrict__ rel, const float* __restrict__ W,
                      const float* __restrict__ We, float* __restrict__ out_tail) {
    int b = blockIdx.x, t = threadIdx.x;
    if (b < 512) {
        size_t tid = (size_t)b * 256 + t, stride = (size_t)512 * 256;
        float4 z = make_float4(0.f, 0.f, 0.f, 0.f);
        float4* hp1 = (float4*)&g_hp1[0][0];
        for (size_t i = tid; i < (size_t)4 * N_NODES * 16; i += stride) hp1[i] = z;
        float4* hp2 = (float4*)&g_hp2[0][0];
        for (size_t i = tid; i < (size_t)2 * N_NODES * 32; i += stride) hp2[i] = z;
        float4* rs1 = (float4*)&g_rowsum1[0][0];
        for (size_t i = tid; i < (size_t)N_NODES; i += stride) rs1[i] = z;
        float4* rs2 = (float4*)&g_rowsum2[0][0];
        for (size_t i = tid; i < (size_t)N_NODES / 2; i += stride) rs2[i] = z;
        if (tid < 2) g_wsum[tid] = 0.f;
    } else if (b < 516) {
        for (int idx = (b - 512) * 256 + t; idx < 512 * 64; idx += 4 * 256) {
            int n = idx >> 6, k = idx & 63;
            int c = n >> 7, rem = n & 127, role = rem >> 6, j = rem & 63;
            const float* A = ((c >> 1) ? a_out : a_in) + (size_t)(c & 1) * 64 * 192;
            g_Wp1[idx] = A[j * 192 + role * 64 + k];
        }
    } else if (b < 518) {
        for (int idx = (b - 516) * 256 + t; idx < 256 * 64; idx += 2 * 256) {
            int n = idx >> 6, k = idx & 63;
            int c = n >> 6, j = n & 63;
            const float* A = ((c >> 1) ? a_out : a_in) + (size_t)(c & 1) * 64 * 192;
            g_WpQ[idx] = A[j * 192 + 128 + k];
        }
    } else if (b < 522) {
        for (int idx = (b - 518) * 256 + t; idx < 256 * 128; idx += 4 * 256) {
            int n = idx >> 7, k = idx & 127;
            int role = n >> 7, j = n & 127;
            g_Wp2[idx] = a_o[j * 384 + role * 128 + k];
        }
    } else if (b < 526) {
        for (int idx = (b - 522) * 256 + t; idx < 128 * 128; idx += 4 * 256) {
            int j = idx >> 7, k = idx & 127;
            g_WeP[idx] = (j < 64) ? We[k * 64 + j] : 0.f;
        }
    } else if (b == 526) {
        for (int n = t; n < 512; n += 256) {
            int c = n >> 7, j = n & 63;
            g_a2cat1[n] = ((c >> 1) ? a2_out : a2_in)[(c & 1) * 64 + j];
        }
        for (int n = t; n < 256; n += 256) {
            int c = n >> 6, j = n & 63;
            g_a2catQ[n] = ((c >> 1) ? a2_out : a2_in)[(c & 1) * 64 + j];
        }
        if (t < 256) g_a2cat2[t] = a2_o[t & 127];
    } else {
        int r = b - 527;  // [0, 200)
        __shared__ float relrow[64];
        __shared__ float rel2row[128];
        __shared__ float red[8];
        if (t < 64) relrow[t] = rel[r * 64 + t];
        __syncthreads();
        // rel2 row (also goes straight to output tail)
        if (t < 128) {
            float acc = 0.f;
            #pragma unroll
            for (int k = 0; k < 64; k++) acc += relrow[k] * W[k * 128 + t];
            rel2row[t] = acc;
            out_tail[(size_t)N_NODES * OUTF + r * 128 + t] = acc;
        }
        __syncthreads();
        // R1proj + Sr1
        {
            int c = t >> 6, j = t & 63;
            const float* A = ((c >> 1) ? a_out : a_in) + (size_t)(c & 1) * 64 * 192;
            float acc = 0.f;
            #pragma unroll
            for (int k = 0; k < 64; k++) acc += relrow[k] * A[j * 192 + 128 + k];
            g_R1proj[c][r * 64 + j] = acc;
            float part = acc * ((c >> 1) ? a2_out : a2_in)[(c & 1) * 64 + j];
            #pragma unroll
            for (int o = 16; o; o >>= 1) part += __shfl_xor_sync(0xffffffffu, part, o);
            if ((t & 31) == 0) red[t >> 5] = part;
        }
        __syncthreads();
        if (t < 4) g_Sr1[r * 4 + t] = red[2 * t] + red[2 * t + 1];
        __syncthreads();
        // R2proj + Srel2
        {
            float part = 0.f;
            if (t < 128) {
                float acc = 0.f;
                #pragma unroll 16
                for (int k = 0; k < 128; k++) acc += rel2row[k] * a_o[t * 384 + 256 + k];
                g_R2proj[r * 128 + t] = acc;
                part = acc * a2_o[t];
            }
            #pragma unroll
            for (int o = 16; o; o >>= 1) part += __shfl_xor_sync(0xffffffffu, part, o);
            if ((t & 31) == 0 && t < 128) red[t >> 5] = part;
        }
        __syncthreads();
        if (t == 0) g_Srel2[r] = red[0] + red[1] + red[2] + red[3];
    }
}

// ---------------- f32x2 packed GEMM: KC=16, 17KB smem, 2 CTAs/SM ----------------
// C[i][jb+j] = sum_k X[i][k] * Wp[(jb+j)][k]
// Adjacent-pair scheme: thread (tx,ty) owns column pairs (2tx+32q, 2tx+32q+1), q=0..3
#define KC 16
__global__ void __launch_bounds__(256, 2)
gemm_f32x2(const float* __restrict__ X,
           const float* __restrict__ Wp,
           float* __restrict__ C,
           const float* __restrict__ a2cat,
           float* __restrict__ sOut,
           int M, int N, int K) {
    __shared__ __align__(16) float Xs[128][17];
    __shared__ __align__(16) float As[KC][130];
    int t = threadIdx.x;
    int tx = t & 15, ty = t >> 4;
    int ib = blockIdx.x * 128;
    int jb = blockIdx.y * 128;
    ull acc[8][4];
    #pragma unroll
    for (int ii = 0; ii < 8; ii++)
        #pragma unroll
        for (int q = 0; q < 4; q++) acc[ii][q] = 0ull;

    for (int kc = 0; kc < K; kc += KC) {
        // X tile: 128 rows x 16 k (512 float4 ops over 256 threads)
        #pragma unroll
        for (int p = t; p < 512; p += 256) {
            int i = p & 127, kq = (p >> 7) * 4;
            int gi = ib + i;
            float4 v = make_float4(0.f, 0.f, 0.f, 0.f);
            if (gi < M) v = *(const float4*)&X[(size_t)gi * K + kc + kq];
            Xs[i][kq + 0] = v.x; Xs[i][kq + 1] = v.y;
            Xs[i][kq + 2] = v.z; Xs[i][kq + 3] = v.w;
        }
        // A tile: transposed scalar store, adjacent columns stay adjacent
        #pragma unroll
        for (int p = t; p < 512; p += 256) {
            int j = p & 127, kq = (p >> 7) * 4;
            float4 v = *(const float4*)&Wp[(size_t)(jb + j) * K + kc + kq];
            As[kq + 0][j] = v.x; As[kq + 1][j] = v.y;
            As[kq + 2][j] = v.z; As[kq + 3][j] = v.w;
        }
        __syncthreads();
        #pragma unroll
        for (int kk = 0; kk < KC; kk++) {
            ull av[4];
            #pragma unroll
            for (int q = 0; q < 4; q++)
                av[q] = *(const ull*)&As[kk][2 * (tx + 16 * q)];
            #pragma unroll
            for (int ii = 0; ii < 8; ii++) {
                float xv = Xs[ty * 8 + ii][kk];
                ull xx;
                asm("mov.b64 %0, {%1, %1};" : "=l"(xx) : "f"(xv));
                #pragma unroll
                for (int q = 0; q < 4; q++)
                    asm("fma.rn.f32x2 %0, %1, %2, %0;"
                        : "+l"(acc[ii][q]) : "l"(xx), "l"(av[q]));
            }
        }
        __syncthreads();
    }
    int nBlk = N >> 6;
    float2 w[4];
    #pragma unroll
    for (int q = 0; q < 4; q++)
        w[q] = *(const float2*)&a2cat[jb + 2 * tx + 32 * q];
    #pragma unroll
    for (int ii = 0; ii < 8; ii++) {
        int gi = ib + ty * 8 + ii;
        float lo[4], hi[4];
        #pragma unroll
        for (int q = 0; q < 4; q++)
            asm("mov.b64 {%0, %1}, %2;" : "=f"(lo[q]), "=f"(hi[q]) : "l"(acc[ii][q]));
        if (gi < M) {
            #pragma unroll
            for (int q = 0; q < 4; q++)
                *(float2*)&C[(size_t)gi * N + jb + 2 * tx + 32 * q] = make_float2(lo[q], hi[q]);
        }
        float s0 = lo[0] * w[0].x + hi[0] * w[0].y + lo[1] * w[1].x + hi[1] * w[1].y;
        float s1 = lo[2] * w[2].x + hi[2] * w[2].y + lo[3] * w[3].x + hi[3] * w[3].y;
        #pragma unroll
        for (int o = 8; o; o >>= 1) {
            s0 += __shfl_xor_sync(0xffffffffu, s0, o);
            s1 += __shfl_xor_sync(0xffffffffu, s1, o);
        }
        if (tx == 0 && gi < M) {
            size_t base = (size_t)gi * nBlk + (jb >> 6);
            sOut[base] = s0;
            sOut[base + 1] = s1;
        }
    }
}

// ---------------- layer-1 edge pass: warp per (combo, edge), factorized score ----------------
__global__ void edge_pass1(const int* __restrict__ el, const int* __restrict__ eln,
                           const int* __restrict__ etn) {
    int c = blockIdx.y;
    int e = blockIdx.x * 8 + (threadIdx.x >> 5);
    if (e >= E_ALL) return;
    int lane = threadIdx.x & 31;
    int dir = c >> 1;
    int i0, i1;
    float qx, qy, sq;
    if (e < E_REAL) {
        i0 = el[e]; i1 = el[E_REAL + e];
        float2 q2 = *(const float2*)&g_Q1all[(size_t)e * 256 + c * 64 + 2 * lane];
        qx = q2.x; qy = q2.y;
        sq = g_SQ1[(size_t)e * 4 + c];
    } else {
        int en = e - E_REAL;
        i0 = eln[en]; i1 = eln[E_NHOP + en];
        int t0 = etn[2 * en], t1 = etn[2 * en + 1];
        float2 qa = *(const float2*)&g_R1proj[c][t0 * 64 + 2 * lane];
        float2 qb = *(const float2*)&g_R1proj[c][t1 * 64 + 2 * lane];
        qx = qa.x + qb.x; qy = qa.y + qb.y;
        sq = g_Sr1[t0 * 4 + c] + g_Sr1[t1 * 4 + c];
    }
    int src = dir ? i1 : i0;
    int dst = dir ? i0 : i1;
    float score = g_S1[(size_t)src * 8 + c * 2] + g_S1[(size_t)dst * 8 + c * 2 + 1] + sq;
    float lk = score > 0.f ? score : ALPHA * score;
    float ev = __expf(-lk);
    float2 d = *(const float2*)&g_P1all[(size_t)dst * 512 + c * 128 + 64 + 2 * lane];
    float* hp = &g_hp1[c][(size_t)src * 64 + 2 * lane];
    RED2(hp, ev * (d.x + qx), ev * (d.y + qy));
    if (lane == 0) atomicAdd(&g_rowsum1[c][src], ev);
}

// ---------------- normalize (+ fold p_src) + elu -> x_s ----------------
__global__ void norm1() {
    int c = blockIdx.y;
    int idx = blockIdx.x * 256 + threadIdx.x;
    if (idx >= N_NODES * 64) return;
    int i = idx >> 6, k = idx & 63;
    float rs = g_rowsum1[c][i];
    float v = g_hp1[c][idx];
    v = (rs > 0.f) ? v / rs + g_P1all[(size_t)i * 512 + c * 128 + k] : 0.f;
    v = (v > 0.f) ? v : expm1f(v);
    int dir = c >> 1, h = c & 1;
    g_xs[dir][(size_t)i * 128 + h * 64 + k] = v;
}

// ---------------- layer-2 edge pass: factorized score ----------------
__global__ void edge_pass2(const int* __restrict__ el, const int* __restrict__ eln,
                           const int* __restrict__ et, const int* __restrict__ etn) {
    int dir = blockIdx.y;
    int e = blockIdx.x * 8 + (threadIdx.x >> 5);
    if (e >= E_ALL) return;
    int lane = threadIdx.x & 31;
    int i0, i1;
    float q0, q1, q2, q3, sq;
    if (e < E_REAL) {
        i0 = el[e]; i1 = el[E_REAL + e];
        int ty = et[e];
        float4 qv = *(const float4*)&g_R2proj[ty * 128 + 4 * lane];
        q0 = qv.x; q1 = qv.y; q2 = qv.z; q3 = qv.w;
        sq = g_Srel2[ty];
    } else {
        int en = e - E_REAL;
        i0 = eln[en]; i1 = eln[E_NHOP + en];
        int t0 = etn[2 * en], t1 = etn[2 * en + 1];
        float4 qa = *(const float4*)&g_R2proj[t0 * 128 + 4 * lane];
        float4 qb = *(const float4*)&g_R2proj[t1 * 128 + 4 * lane];
        q0 = qa.x + qb.x; q1 = qa.y + qb.y; q2 = qa.z + qb.z; q3 = qa.w + qb.w;
        sq = g_Srel2[t0] + g_Srel2[t1];
    }
    int seg = dir ? i1 : i0;
    int nbr = dir ? i0 : i1;
    float4 sA = *(const float4*)&g_S2[dir][(size_t)seg * 4];
    float4 sB = *(const float4*)&g_S2[dir][(size_t)nbr * 4];
    float score = sA.x + sA.y + sB.z + sB.w + sq;
    float lk = score > 0.f ? score : ALPHA * score;
    float ev = __expf(-lk);
    float4 dv = *(const float4*)&g_P2all[dir][(size_t)nbr * 256 + 128 + 4 * lane];
    float* hp = &g_hp2[dir][(size_t)seg * 128 + 4 * lane];
    RED4(hp, ev * (dv.x + q0), ev * (dv.y + q1), ev * (dv.z + q2), ev * (dv.w + q3));
    if (lane == 0) atomicAdd(&g_rowsum2[dir][seg], ev);
}

// ---------------- layer-2 normalize (+ fold p_seg) + elu -> y ----------------
__global__ void norm2() {
    int xs = blockIdx.y;
    int idx = blockIdx.x * 256 + threadIdx.x;
    if (idx >= N_NODES * 128) return;
    int i = idx >> 7, k = idx & 127;
    float rs = g_rowsum2[xs][i];
    float v = (rs > 0.f)
        ? g_hp2[xs][idx] / rs + g_P2all[xs][(size_t)i * 256 + k]
        : 0.f;
    v = (v > 0.f) ? v : expm1f(v);
    g_y[xs][idx] = v;
}

// ---------------- wdot: wp[n] = sum_j tanh(tw[n][j] + be[j]) * qe[j], block-reduced ----------------
__global__ void wdot(const float* __restrict__ be, const float* __restrict__ qe) {
    int w = threadIdx.x >> 5;
    int lane = threadIdx.x & 31;
    int n = blockIdx.x * 8 + w;           // [0, 100000)
    int xs = n >= N_NODES;
    float wp = 0.f;
    #pragma unroll
    for (int half = 0; half < 2; half++) {
        int j = lane + 32 * half;
        float v = g_tw[(size_t)n * 128 + j] + be[j];
        wp += tanhf(v) * qe[j];
    }
    #pragma unroll
    for (int o = 16; o; o >>= 1) wp += __shfl_xor_sync(0xffffffffu, wp, o);
    __shared__ float red[8];
    if (lane == 0) red[w] = wp;
    __syncthreads();
    if (threadIdx.x == 0) {
        float s = 0.f;
        #pragma unroll
        for (int u = 0; u < 8; u++) s += red[u];
        atomicAdd(&g_wsum[xs], s);
    }
}

// ---------------- beta + combine (fused) ----------------
__global__ void combine(float* __restrict__ out) {
    float m0 = g_wsum[0] / (float)N_NODES;
    float m1 = g_wsum[1] / (float)N_NODES;
    float mx = fmaxf(m0, m1);
    float e0 = expf(m0 - mx), e1 = expf(m1 - mx);
    float b0 = e0 / (e0 + e1), b1 = e1 / (e0 + e1);
    size_t i = (size_t)blockIdx.x * 256 + threadIdx.x;
    if (i >= (size_t)N_NODES * OUTF) return;
    out[i] = b0 * g_y[0][i] + b1 * g_y[1][i];
}

// ---------------- launch ----------------
extern "C" void kernel_launch(void* const* d_in, const int* in_sizes, int n_in,
                              void* d_out, int out_size) {
    const float* ent   = (const float*)d_in[0];
    const float* rel   = (const float*)d_in[1];
    const int*   el    = (const int*)d_in[2];
    const int*   et    = (const int*)d_in[3];
    const float* eemb  = (const float*)d_in[4];
    const int*   eln   = (const int*)d_in[5];
    const int*   etn   = (const int*)d_in[6];
    const float* a_in  = (const float*)d_in[7];
    const float* a2_in = (const float*)d_in[8];
    const float* a_out = (const float*)d_in[9];
    const float* a2_out= (const float*)d_in[10];
    const float* a_o   = (const float*)d_in[11];
    const float* a2_o  = (const float*)d_in[12];
    const float* W     = (const float*)d_in[13];
    const float* We    = (const float*)d_in[14];
    const float* be    = (const float*)d_in[15];
    const float* qe    = (const float*)d_in[16];
    float* out = (float*)d_out;

    float *p1 = 0, *q1 = 0, *xsb = 0, *p2 = 0, *wp1 = 0, *wpq = 0, *wp2 = 0, *wep = 0;
    float *a2c1 = 0, *a2cq = 0, *a2c2 = 0, *s1 = 0, *sq1 = 0, *s2 = 0, *yb = 0, *tw = 0, *sd = 0;
    cudaGetSymbolAddress((void**)&p1, g_P1all);
    cudaGetSymbolAddress((void**)&q1, g_Q1all);
    cudaGetSymbolAddress((void**)&xsb, g_xs);
    cudaGetSymbolAddress((void**)&p2, g_P2all);
    cudaGetSymbolAddress((void**)&wp1, g_Wp1);
    cudaGetSymbolAddress((void**)&wpq, g_WpQ);
    cudaGetSymbolAddress((void**)&wp2, g_Wp2);
    cudaGetSymbolAddress((void**)&wep, g_WeP);
    cudaGetSymbolAddress((void**)&a2c1, g_a2cat1);
    cudaGetSymbolAddress((void**)&a2cq, g_a2catQ);
    cudaGetSymbolAddress((void**)&a2c2, g_a2cat2);
    cudaGetSymbolAddress((void**)&s1, g_S1);
    cudaGetSymbolAddress((void**)&sq1, g_SQ1);
    cudaGetSymbolAddress((void**)&s2, g_S2);
    cudaGetSymbolAddress((void**)&yb, g_y);
    cudaGetSymbolAddress((void**)&tw, g_tw);
    cudaGetSymbolAddress((void**)&sd, g_Sdummy);

    setup<<<727, 256>>>(a_in, a_out, a_o, a2_in, a2_out, a2_o, rel, W, We, out);

    // layer-1 projections with fused score-dot epilogues
    gemm_f32x2<<<dim3((N_NODES + 127) / 128, 4), 256>>>(ent, wp1, p1, a2c1, s1,
                                                        N_NODES, 512, 64);
    gemm_f32x2<<<dim3((E_REAL + 127) / 128, 2), 256>>>(eemb, wpq, q1, a2cq, sq1,
                                                       E_REAL, 256, 64);

    edge_pass1<<<dim3(E_ALL / 8, 4), 256>>>(el, eln, etn);
    norm1<<<dim3((N_NODES * 64 + 255) / 256, 4), 256>>>();

    // layer-2 projections
    for (int xs = 0; xs < 2; xs++)
        gemm_f32x2<<<dim3((N_NODES + 127) / 128, 2), 256>>>(
            xsb + (size_t)xs * N_NODES * 128, wp2,
            p2 + (size_t)xs * N_NODES * 256,
            a2c2, s2 + (size_t)xs * N_NODES * 4,
            N_NODES, 256, 128);

    edge_pass2<<<dim3(E_ALL / 8, 2), 256>>>(el, eln, et, etn);
    norm2<<<dim3((N_NODES * 128 + 255) / 256, 2), 256>>>();

    // y @ WeP  (both xs stacked: M = 100000, N = 128 [cols 64+ are zero], K = 128)
    gemm_f32x2<<<dim3((2 * N_NODES + 127) / 128, 1), 256>>>(yb, wep, tw, a2c2, sd,
                                                            2 * N_NODES, 128, 128);
    wdot<<<2 * N_NODES / 8, 256>>>(be, qe);
    combine<<<(N_NODES * OUTF + 255) / 256, 256>>>(out);
}

// round 9
// speedup vs baseline: 1.5075x; 1.0157x over previous
#include <cuda_runtime.h>
#include <math.h>

#define N_NODES 50000
#define NFEAT   64
#define NHID    64
#define E_REAL  200000
#define E_NHOP  40000
#define E_ALL   240000
#define N_REL   200
#define OUTF    128
#define ALPHA   0.2f

typedef unsigned long long ull;

// ---------------- device scratch ----------------
// P1 layout: [i][dir*256 + role*128 + h*64 + j]
__device__ __align__(16) float g_P1all[(size_t)N_NODES * 512];
// Q1 layout: [e][c*64 + j], c = dir*2 + h  (dir-major contiguous pairs)
__device__ __align__(16) float g_Q1all[(size_t)E_REAL * 256];
// R1proj flat: [r*256 + c*64 + j]
__device__ __align__(16) float g_R1proj[N_REL * 256];
__device__ __align__(16) float g_R2proj[N_REL * OUTF];
__device__ __align__(16) float g_rowsum1T[(size_t)N_NODES * 4];    // [i*4 + c]
__device__ __align__(16) float g_hp1[2][(size_t)N_NODES * 128];    // [dir][i*128 + h*64 + j]
__device__ __align__(16) float g_xs[2][(size_t)N_NODES * OUTF];
__device__ __align__(16) float g_P2all[2][(size_t)N_NODES * 256];  // [xs][i][role*128 + j]
__device__ float g_rowsum2[2][N_NODES];
__device__ __align__(16) float g_hp2[2][(size_t)N_NODES * OUTF];
__device__ __align__(16) float g_y[2][(size_t)N_NODES * OUTF];
__device__ __align__(16) float g_tw[(size_t)2 * N_NODES * 128];
__device__ float g_wsum[2];
// packed weights (row-major [n][K])
__device__ __align__(16) float g_Wp1[512 * 64];
__device__ __align__(16) float g_WpQ[256 * 64];
__device__ __align__(16) float g_Wp2[256 * 128];
__device__ __align__(16) float g_WeP[128 * 128];
// factorized attention scalars
__device__ __align__(16) float g_S1[(size_t)N_NODES * 8];   // [i*8 + dir*4 + role*2 + h]
__device__ __align__(16) float g_SQ1[(size_t)E_REAL * 4];   // [e*4 + c]
__device__ __align__(16) float g_Sr1[N_REL * 4];            // [r*4 + c]
__device__ __align__(16) float g_S2[2][(size_t)N_NODES * 4];
__device__ float g_Srel2[N_REL];
__device__ __align__(16) float g_Sdummy[(size_t)2 * N_NODES * 2];
// per-column dot weights aligned with GEMM outputs
__device__ __align__(16) float g_a2cat1[512];
__device__ __align__(16) float g_a2catQ[256];
__device__ __align__(16) float g_a2cat2[256];

#define RED4(ptr, a, b, c, d) \
    asm volatile("red.global.add.v4.f32 [%0], {%1, %2, %3, %4};" :: "l"(ptr), "f"(a), "f"(b), "f"(c), "f"(d) : "memory")

// ---------------- fused setup ----------------
// blocks: [0,512) zero | 512-515 Wp1 | 516-517 WpQ | 518-521 Wp2 | 522-525 WeP
//         | 526 a2cat | [527, 727) relation blocks
__global__ void setup(const float* __restrict__ a_in, const float* __restrict__ a_out,
                      const float* __restrict__ a_o,
                      const float* __restrict__ a2_in, const float* __restrict__ a2_out,
                      const float* __restrict__ a2_o,
                      const float* __restrict__ rel, const float* __restrict__ W,
                      const float* __restrict__ We, float* __restrict__ out_tail) {
    int b = blockIdx.x, t = threadIdx.x;
    if (b < 512) {
        size_t tid = (size_t)b * 256 + t, stride = (size_t)512 * 256;
        float4 z = make_float4(0.f, 0.f, 0.f, 0.f);
        float4* hp1 = (float4*)&g_hp1[0][0];
        for (size_t i = tid; i < (size_t)2 * N_NODES * 32; i += stride) hp1[i] = z;
        float4* hp2 = (float4*)&g_hp2[0][0];
        for (size_t i = tid; i < (size_t)2 * N_NODES * 32; i += stride) hp2[i] = z;
        float4* rs1 = (float4*)&g_rowsum1T[0];
        for (size_t i = tid; i < (size_t)N_NODES; i += stride) rs1[i] = z;
        float4* rs2 = (float4*)&g_rowsum2[0][0];
        for (size_t i = tid; i < (size_t)N_NODES / 2; i += stride) rs2[i] = z;
        if (tid < 2) g_wsum[tid] = 0.f;
    } else if (b < 516) {
        // Wp1: n = dir*256 + role*128 + h*64 + j
        for (int idx = (b - 512) * 256 + t; idx < 512 * 64; idx += 4 * 256) {
            int n = idx >> 6, k = idx & 63;
            int dir = n >> 8, role = (n >> 7) & 1, h = (n >> 6) & 1, j = n & 63;
            const float* A = (dir ? a_out : a_in) + (size_t)h * 64 * 192;
            g_Wp1[idx] = A[j * 192 + role * 64 + k];
        }
    } else if (b < 518) {
        for (int idx = (b - 516) * 256 + t; idx < 256 * 64; idx += 2 * 256) {
            int n = idx >> 6, k = idx & 63;
            int c = n >> 6, j = n & 63;
            const float* A = ((c >> 1) ? a_out : a_in) + (size_t)(c & 1) * 64 * 192;
            g_WpQ[idx] = A[j * 192 + 128 + k];
        }
    } else if (b < 522) {
        for (int idx = (b - 518) * 256 + t; idx < 256 * 128; idx += 4 * 256) {
            int n = idx >> 7, k = idx & 127;
            int role = n >> 7, j = n & 127;
            g_Wp2[idx] = a_o[j * 384 + role * 128 + k];
        }
    } else if (b < 526) {
        for (int idx = (b - 522) * 256 + t; idx < 128 * 128; idx += 4 * 256) {
            int j = idx >> 7, k = idx & 127;
            g_WeP[idx] = (j < 64) ? We[k * 64 + j] : 0.f;
        }
    } else if (b == 526) {
        for (int n = t; n < 512; n += 256) {
            int dir = n >> 8, h = (n >> 6) & 1, j = n & 63;
            g_a2cat1[n] = (dir ? a2_out : a2_in)[h * 64 + j];
        }
        for (int n = t; n < 256; n += 256) {
            int c = n >> 6, j = n & 63;
            g_a2catQ[n] = ((c >> 1) ? a2_out : a2_in)[(c & 1) * 64 + j];
        }
        if (t < 256) g_a2cat2[t] = a2_o[t & 127];
    } else {
        int r = b - 527;  // [0, 200)
        __shared__ float relrow[64];
        __shared__ float rel2row[128];
        __shared__ float red[8];
        if (t < 64) relrow[t] = rel[r * 64 + t];
        __syncthreads();
        if (t < 128) {
            float acc = 0.f;
            #pragma unroll
            for (int k = 0; k < 64; k++) acc += relrow[k] * W[k * 128 + t];
            rel2row[t] = acc;
            out_tail[(size_t)N_NODES * OUTF + r * 128 + t] = acc;
        }
        __syncthreads();
        // R1proj + Sr1 (t = c*64 + j)
        {
            int c = t >> 6, j = t & 63;
            const float* A = ((c >> 1) ? a_out : a_in) + (size_t)(c & 1) * 64 * 192;
            float acc = 0.f;
            #pragma unroll
            for (int k = 0; k < 64; k++) acc += relrow[k] * A[j * 192 + 128 + k];
            g_R1proj[r * 256 + t] = acc;
            float part = acc * ((c >> 1) ? a2_out : a2_in)[(c & 1) * 64 + j];
            #pragma unroll
            for (int o = 16; o; o >>= 1) part += __shfl_xor_sync(0xffffffffu, part, o);
            if ((t & 31) == 0) red[t >> 5] = part;
        }
        __syncthreads();
        if (t < 4) g_Sr1[r * 4 + t] = red[2 * t] + red[2 * t + 1];
        __syncthreads();
        // R2proj + Srel2
        {
            float part = 0.f;
            if (t < 128) {
                float acc = 0.f;
                #pragma unroll 16
                for (int k = 0; k < 128; k++) acc += rel2row[k] * a_o[t * 384 + 256 + k];
                g_R2proj[r * 128 + t] = acc;
                part = acc * a2_o[t];
            }
            #pragma unroll
            for (int o = 16; o; o >>= 1) part += __shfl_xor_sync(0xffffffffu, part, o);
            if ((t & 31) == 0 && t < 128) red[t >> 5] = part;
        }
        __syncthreads();
        if (t == 0) g_Srel2[r] = red[0] + red[1] + red[2] + red[3];
    }
}

// ---------------- f32x2 packed GEMM: KC=16, pre-duplicated X, 24.5KB, 2 CTAs/SM ----------------
#define KC 16
__global__ void __launch_bounds__(256, 2)
gemm_f32x2(const float* __restrict__ X,
           const float* __restrict__ Wp,
           float* __restrict__ C,
           const float* __restrict__ a2cat,
           float* __restrict__ sOut,
           int M, int N, int K) {
    __shared__ __align__(16) float2 Xs2[KC][130];  // {x,x} pre-dup
    __shared__ __align__(16) float  As[KC][132];   // adjacent-pair columns
    int t = threadIdx.x;
    int tx = t & 15, ty = t >> 4;
    int ib = blockIdx.x * 128;
    int jb = blockIdx.y * 128;
    ull acc[8][4];
    #pragma unroll
    for (int ii = 0; ii < 8; ii++)
        #pragma unroll
        for (int q = 0; q < 4; q++) acc[ii][q] = 0ull;

    for (int kc = 0; kc < K; kc += KC) {
        #pragma unroll
        for (int p = t; p < 512; p += 256) {
            int i = p & 127, kq = (p >> 7) * 4;
            int gi = ib + i;
            float4 v = make_float4(0.f, 0.f, 0.f, 0.f);
            if (gi < M) v = *(const float4*)&X[(size_t)gi * K + kc + kq];
            Xs2[kq + 0][i] = make_float2(v.x, v.x);
            Xs2[kq + 1][i] = make_float2(v.y, v.y);
            Xs2[kq + 2][i] = make_float2(v.z, v.z);
            Xs2[kq + 3][i] = make_float2(v.w, v.w);
        }
        #pragma unroll
        for (int p = t; p < 512; p += 256) {
            int j = p & 127, kq = (p >> 7) * 4;
            float4 v = *(const float4*)&Wp[(size_t)(jb + j) * K + kc + kq];
            As[kq + 0][j] = v.x; As[kq + 1][j] = v.y;
            As[kq + 2][j] = v.z; As[kq + 3][j] = v.w;
        }
        __syncthreads();
        #pragma unroll
        for (int kk = 0; kk < KC; kk++) {
            ull av[4];
            #pragma unroll
            for (int q = 0; q < 4; q++)
                av[q] = *(const ull*)&As[kk][2 * (tx + 16 * q)];
            #pragma unroll
            for (int ii = 0; ii < 8; ii++) {
                ull xx = *(const ull*)&Xs2[kk][ty * 8 + ii];
                #pragma unroll
                for (int q = 0; q < 4; q++)
                    asm("fma.rn.f32x2 %0, %1, %2, %0;"
                        : "+l"(acc[ii][q]) : "l"(xx), "l"(av[q]));
            }
        }
        __syncthreads();
    }
    int nBlk = N >> 6;
    float2 w[4];
    #pragma unroll
    for (int q = 0; q < 4; q++)
        w[q] = *(const float2*)&a2cat[jb + 2 * tx + 32 * q];
    #pragma unroll
    for (int ii = 0; ii < 8; ii++) {
        int gi = ib + ty * 8 + ii;
        float lo[4], hi[4];
        #pragma unroll
        for (int q = 0; q < 4; q++)
            asm("mov.b64 {%0, %1}, %2;" : "=f"(lo[q]), "=f"(hi[q]) : "l"(acc[ii][q]));
        if (gi < M) {
            #pragma unroll
            for (int q = 0; q < 4; q++)
                *(float2*)&C[(size_t)gi * N + jb + 2 * tx + 32 * q] = make_float2(lo[q], hi[q]);
        }
        float s0 = lo[0] * w[0].x + hi[0] * w[0].y + lo[1] * w[1].x + hi[1] * w[1].y;
        float s1 = lo[2] * w[2].x + hi[2] * w[2].y + lo[3] * w[3].x + hi[3] * w[3].y;
        #pragma unroll
        for (int o = 8; o; o >>= 1) {
            s0 += __shfl_xor_sync(0xffffffffu, s0, o);
            s1 += __shfl_xor_sync(0xffffffffu, s1, o);
        }
        if (tx == 0 && gi < M) {
            size_t base = (size_t)gi * nBlk + (jb >> 6);
            sOut[base] = s0;
            sOut[base + 1] = s1;
        }
    }
}

// ---------------- layer-1 edge pass: warp per (dir, edge), BOTH heads, factorized ----------------
__global__ void edge_pass1(const int* __restrict__ el, const int* __restrict__ eln,
                           const int* __restrict__ etn) {
    int dir = blockIdx.y;
    int e = blockIdx.x * 8 + (threadIdx.x >> 5);
    int lane = threadIdx.x & 31;
    int h = lane >> 4;
    int jj = 4 * (lane & 15);
    int i0, i1;
    float4 q;
    float sq;
    if (e < E_REAL) {
        i0 = el[e]; i1 = el[E_REAL + e];
        q = *(const float4*)&g_Q1all[(size_t)e * 256 + dir * 128 + h * 64 + jj];
        sq = g_SQ1[(size_t)e * 4 + dir * 2 + h];
    } else {
        int en = e - E_REAL;
        i0 = eln[en]; i1 = eln[E_NHOP + en];
        int t0 = etn[2 * en], t1 = etn[2 * en + 1];
        float4 qa = *(const float4*)&g_R1proj[t0 * 256 + dir * 128 + h * 64 + jj];
        float4 qb = *(const float4*)&g_R1proj[t1 * 256 + dir * 128 + h * 64 + jj];
        q.x = qa.x + qb.x; q.y = qa.y + qb.y; q.z = qa.z + qb.z; q.w = qa.w + qb.w;
        sq = g_Sr1[t0 * 4 + dir * 2 + h] + g_Sr1[t1 * 4 + dir * 2 + h];
    }
    int src = dir ? i1 : i0;
    int dst = dir ? i0 : i1;
    float score = g_S1[(size_t)src * 8 + dir * 4 + h]
                + g_S1[(size_t)dst * 8 + dir * 4 + 2 + h] + sq;
    float lk = score > 0.f ? score : ALPHA * score;
    float ev = __expf(-lk);
    float4 d = *(const float4*)&g_P1all[(size_t)dst * 512 + dir * 256 + 128 + h * 64 + jj];
    float* hp = &g_hp1[dir][(size_t)src * 128 + h * 64 + jj];
    RED4(hp, ev * (d.x + q.x), ev * (d.y + q.y), ev * (d.z + q.z), ev * (d.w + q.w));
    if ((lane & 15) == 0) atomicAdd(&g_rowsum1T[(size_t)src * 4 + dir * 2 + h], ev);
}

// ---------------- normalize (+ fold p_src) + elu -> x_s ----------------
__global__ void norm1() {
    int dir = blockIdx.y;
    int idx = blockIdx.x * 256 + threadIdx.x;
    if (idx >= N_NODES * 128) return;
    int i = idx >> 7, kk = idx & 127;
    float rs = g_rowsum1T[(size_t)i * 4 + dir * 2 + (kk >> 6)];
    float v = g_hp1[dir][idx];
    v = (rs > 0.f) ? v / rs + g_P1all[(size_t)i * 512 + dir * 256 + kk] : 0.f;
    v = (v > 0.f) ? v : expm1f(v);
    g_xs[dir][idx] = v;
}

// ---------------- layer-2 edge pass: factorized score ----------------
__global__ void edge_pass2(const int* __restrict__ el, const int* __restrict__ eln,
                           const int* __restrict__ et, const int* __restrict__ etn) {
    int dir = blockIdx.y;
    int e = blockIdx.x * 8 + (threadIdx.x >> 5);
    if (e >= E_ALL) return;
    int lane = threadIdx.x & 31;
    int i0, i1;
    float q0, q1, q2, q3, sq;
    if (e < E_REAL) {
        i0 = el[e]; i1 = el[E_REAL + e];
        int ty = et[e];
        float4 qv = *(const float4*)&g_R2proj[ty * 128 + 4 * lane];
        q0 = qv.x; q1 = qv.y; q2 = qv.z; q3 = qv.w;
        sq = g_Srel2[ty];
    } else {
        int en = e - E_REAL;
        i0 = eln[en]; i1 = eln[E_NHOP + en];
        int t0 = etn[2 * en], t1 = etn[2 * en + 1];
        float4 qa = *(const float4*)&g_R2proj[t0 * 128 + 4 * lane];
        float4 qb = *(const float4*)&g_R2proj[t1 * 128 + 4 * lane];
        q0 = qa.x + qb.x; q1 = qa.y + qb.y; q2 = qa.z + qb.z; q3 = qa.w + qb.w;
        sq = g_Srel2[t0] + g_Srel2[t1];
    }
    int seg = dir ? i1 : i0;
    int nbr = dir ? i0 : i1;
    float4 sA = *(const float4*)&g_S2[dir][(size_t)seg * 4];
    float4 sB = *(const float4*)&g_S2[dir][(size_t)nbr * 4];
    float score = sA.x + sA.y + sB.z + sB.w + sq;
    float lk = score > 0.f ? score : ALPHA * score;
    float ev = __expf(-lk);
    float4 dv = *(const float4*)&g_P2all[dir][(size_t)nbr * 256 + 128 + 4 * lane];
    float* hp = &g_hp2[dir][(size_t)seg * 128 + 4 * lane];
    RED4(hp, ev * (dv.x + q0), ev * (dv.y + q1), ev * (dv.z + q2), ev * (dv.w + q3));
    if (lane == 0) atomicAdd(&g_rowsum2[dir][seg], ev);
}

// ---------------- layer-2 normalize (+ fold p_seg) + elu -> y ----------------
__global__ void norm2() {
    int xs = blockIdx.y;
    int idx = blockIdx.x * 256 + threadIdx.x;
    if (idx >= N_NODES * 128) return;
    int i = idx >> 7, k = idx & 127;
    float rs = g_rowsum2[xs][i];
    float v = (rs > 0.f)
        ? g_hp2[xs][idx] / rs + g_P2all[xs][(size_t)i * 256 + k]
        : 0.f;
    v = (v > 0.f) ? v : expm1f(v);
    g_y[xs][idx] = v;
}

// ---------------- wdot ----------------
__global__ void wdot(const float* __restrict__ be, const float* __restrict__ qe) {
    int w = threadIdx.x >> 5;
    int lane = threadIdx.x & 31;
    int n = blockIdx.x * 8 + w;
    int xs = n >= N_NODES;
    float wp = 0.f;
    #pragma unroll
    for (int half = 0; half < 2; half++) {
        int j = lane + 32 * half;
        float v = g_tw[(size_t)n * 128 + j] + be[j];
        wp += tanhf(v) * qe[j];
    }
    #pragma unroll
    for (int o = 16; o; o >>= 1) wp += __shfl_xor_sync(0xffffffffu, wp, o);
    __shared__ float red[8];
    if (lane == 0) red[w] = wp;
    __syncthreads();
    if (threadIdx.x == 0) {
        float s = 0.f;
        #pragma unroll
        for (int u = 0; u < 8; u++) s += red[u];
        atomicAdd(&g_wsum[xs], s);
    }
}

// ---------------- beta + combine (fused) ----------------
__global__ void combine(float* __restrict__ out) {
    float m0 = g_wsum[0] / (float)N_NODES;
    float m1 = g_wsum[1] / (float)N_NODES;
    float mx = fmaxf(m0, m1);
    float e0 = expf(m0 - mx), e1 = expf(m1 - mx);
    float b0 = e0 / (e0 + e1), b1 = e1 / (e0 + e1);
    size_t i = (size_t)blockIdx.x * 256 + threadIdx.x;
    if (i >= (size_t)N_NODES * OUTF) return;
    out[i] = b0 * g_y[0][i] + b1 * g_y[1][i];
}

// ---------------- launch ----------------
extern "C" void kernel_launch(void* const* d_in, const int* in_sizes, int n_in,
                              void* d_out, int out_size) {
    const float* ent   = (const float*)d_in[0];
    const float* rel   = (const float*)d_in[1];
    const int*   el    = (const int*)d_in[2];
    const int*   et    = (const int*)d_in[3];
    const float* eemb  = (const float*)d_in[4];
    const int*   eln   = (const int*)d_in[5];
    const int*   etn   = (const int*)d_in[6];
    const float* a_in  = (const float*)d_in[7];
    const float* a2_in = (const float*)d_in[8];
    const float* a_out = (const float*)d_in[9];
    const float* a2_out= (const float*)d_in[10];
    const float* a_o   = (const float*)d_in[11];
    const float* a2_o  = (const float*)d_in[12];
    const float* W     = (const float*)d_in[13];
    const float* We    = (const float*)d_in[14];
    const float* be    = (const float*)d_in[15];
    const float* qe    = (const float*)d_in[16];
    float* out = (float*)d_out;

    float *p1 = 0, *q1 = 0, *xsb = 0, *p2 = 0, *wp1 = 0, *wpq = 0, *wp2 = 0, *wep = 0;
    float *a2c1 = 0, *a2cq = 0, *a2c2 = 0, *s1 = 0, *sq1 = 0, *s2 = 0, *yb = 0, *tw = 0, *sd = 0;
    cudaGetSymbolAddress((void**)&p1, g_P1all);
    cudaGetSymbolAddress((void**)&q1, g_Q1all);
    cudaGetSymbolAddress((void**)&xsb, g_xs);
    cudaGetSymbolAddress((void**)&p2, g_P2all);
    cudaGetSymbolAddress((void**)&wp1, g_Wp1);
    cudaGetSymbolAddress((void**)&wpq, g_WpQ);
    cudaGetSymbolAddress((void**)&wp2, g_Wp2);
    cudaGetSymbolAddress((void**)&wep, g_WeP);
    cudaGetSymbolAddress((void**)&a2c1, g_a2cat1);
    cudaGetSymbolAddress((void**)&a2cq, g_a2catQ);
    cudaGetSymbolAddress((void**)&a2c2, g_a2cat2);
    cudaGetSymbolAddress((void**)&s1, g_S1);
    cudaGetSymbolAddress((void**)&sq1, g_SQ1);
    cudaGetSymbolAddress((void**)&s2, g_S2);
    cudaGetSymbolAddress((void**)&yb, g_y);
    cudaGetSymbolAddress((void**)&tw, g_tw);
    cudaGetSymbolAddress((void**)&sd, g_Sdummy);

    setup<<<727, 256>>>(a_in, a_out, a_o, a2_in, a2_out, a2_o, rel, W, We, out);

    gemm_f32x2<<<dim3((N_NODES + 127) / 128, 4), 256>>>(ent, wp1, p1, a2c1, s1,
                                                        N_NODES, 512, 64);
    gemm_f32x2<<<dim3((E_REAL + 127) / 128, 2), 256>>>(eemb, wpq, q1, a2cq, sq1,
                                                       E_REAL, 256, 64);

    edge_pass1<<<dim3(E_ALL / 8, 2), 256>>>(el, eln, etn);
    norm1<<<dim3((N_NODES * 128 + 255) / 256, 2), 256>>>();

    for (int xs = 0; xs < 2; xs++)
        gemm_f32x2<<<dim3((N_NODES + 127) / 128, 2), 256>>>(
            xsb + (size_t)xs * N_NODES * 128, wp2,
            p2 + (size_t)xs * N_NODES * 256,
            a2c2, s2 + (size_t)xs * N_NODES * 4,
            N_NODES, 256, 128);

    edge_pass2<<<dim3(E_ALL / 8, 2), 256>>>(el, eln, et, etn);
    norm2<<<dim3((N_NODES * 128 + 255) / 256, 2), 256>>>();

    gemm_f32x2<<<dim3((2 * N_NODES + 127) / 128, 1), 256>>>(yb, wep, tw, a2c2, sd,
                                                            2 * N_NODES, 128, 128);
    wdot<<<2 * N_NODES / 8, 256>>>(be, qe);
    combine<<<(N_NODES * OUTF + 255) / 256, 256>>>(out);
}